// round 7
// baseline (speedup 1.0000x reference)
#include <cuda_runtime.h>
#include <cuda_bf16.h>
#include <math.h>
#include <stdint.h>

#define HID   1024
#define BATCH 32
#define SEQ   512
#define RIMG  196
#define NCT   8
#define MT    128
#define NT    128
#define KC    32                     // int8 K per chunk = one IMMA K
#define NCHUNK (HID / KC)
#define ROWB  48                     // 32B data + 16B pad
#define VERB  (128 * ROWB)           // 6144 B per matrix version
#define STAGEB (4 * VERB)            // Aq1, Aq2, Bq1, Bq2 = 24576
#define WV_OFF  (2 * STAGEB)         // 49152
#define RED_OFF (WV_OFF + 512)
#define SMEM_DYN (RED_OFF + 2048 + 256)

#define QA_BOUND 6.0f
#define QW_BOUND (6.0f / 32.0f)

// ---------------- scratch ----------------
__device__ float g_part1[NCT * BATCH * RIMG];
__device__ float g_part2[NCT * BATCH * SEQ];
__device__ float g_w1[BATCH * RIMG];
__device__ float g_w2[BATCH * SEQ];
__device__ float g_v[BATCH * HID];
__device__ float g_u[BATCH * HID];

__device__ char g_dns_q1[BATCH * SEQ * HID];
__device__ char g_dns_q2[BATCH * SEQ * HID];
__device__ char g_img_q1[BATCH * RIMG * HID];
__device__ char g_img_q2[BATCH * RIMG * HID];
__device__ char g_wi_q1[HID * HID];
__device__ char g_wi_q2[HID * HID];
__device__ char g_wd_q1[HID * HID];
__device__ char g_wd_q2[HID * HID];

// ---------------- helpers ----------------
__device__ __forceinline__ uint32_t smem_u32(const void* p) {
    uint32_t a;
    asm("{ .reg .u64 t; cvta.to.shared.u64 t, %1; cvt.u32.u64 %0, t; }" : "=r"(a) : "l"(p));
    return a;
}
__device__ __forceinline__ void ldsm4(uint32_t* r, uint32_t addr) {
    asm volatile("ldmatrix.sync.aligned.m8n8.x4.shared.b16 {%0,%1,%2,%3}, [%4];"
                 : "=r"(r[0]), "=r"(r[1]), "=r"(r[2]), "=r"(r[3]) : "r"(addr));
}
__device__ __forceinline__ void imma(int* c, const uint32_t* a, uint32_t b0, uint32_t b1) {
    asm volatile(
        "mma.sync.aligned.m16n8k32.row.col.s32.s8.s8.s32 "
        "{%0,%1,%2,%3}, {%4,%5,%6,%7}, {%8,%9}, {%0,%1,%2,%3};"
        : "+r"(c[0]), "+r"(c[1]), "+r"(c[2]), "+r"(c[3])
        : "r"(a[0]), "r"(a[1]), "r"(a[2]), "r"(a[3]), "r"(b0), "r"(b1));
}
#define CP16(s, g) \
    asm volatile("cp.async.cg.shared.global [%0], [%1], 16;" :: "r"(s), "l"(g) : "memory")
#define CP_COMMIT() asm volatile("cp.async.commit_group;" ::: "memory")

__device__ __forceinline__ float fast_tanh(float x) {
    return 1.f - 2.f / (__expf(2.f * x) + 1.f);
}
__device__ __forceinline__ int clamp127(int q) {
    return max(-127, min(127, q));
}

// ---------------------------------------------------------------------------
// fp32 -> 2-limb int8 quantization: x ~= D*(q1 + q2/128). 16 elems/thread.
// ---------------------------------------------------------------------------
__global__ __launch_bounds__(256)
void quantize(const float* __restrict__ in, uint32_t* __restrict__ q1o,
              uint32_t* __restrict__ q2o, float invD)
{
    const int i = blockIdx.x * blockDim.x + threadIdx.x;
    const float4* p = (const float4*)in + (size_t)i * 4;
    uint32_t w1[4], w2[4];
#pragma unroll
    for (int j = 0; j < 4; j++) {
        float4 v = p[j];
        float f[4] = {v.x, v.y, v.z, v.w};
        uint32_t b1 = 0, b2 = 0;
#pragma unroll
        for (int k = 0; k < 4; k++) {
            float y = f[k] * invD;
            int q = clamp127(__float2int_rn(y));
            int r = clamp127(__float2int_rn((y - (float)q) * 128.f));
            b1 |= (uint32_t)(q & 0xff) << (k * 8);
            b2 |= (uint32_t)(r & 0xff) << (k * 8);
        }
        w1[j] = b1; w2[j] = b2;
    }
    ((uint4*)q1o)[i] = make_uint4(w1[0], w1[1], w1[2], w1[3]);
    ((uint4*)q2o)[i] = make_uint4(w2[0], w2[1], w2[2], w2[3]);
}

// ---------------------------------------------------------------------------
// int8 2-limb IMMA GEMM(X·Wᵀ) + dequant + tanh + dot(wvec) per 128-col tile.
// 512 threads, warp tile 32x32, 2-stage cp.async pipeline.
// ---------------------------------------------------------------------------
__global__ __launch_bounds__(512, 1)
void gemm_imma(const char* __restrict__ Xq1, const char* __restrict__ Xq2,
               const char* __restrict__ Wq1, const char* __restrict__ Wq2,
               const float* __restrict__ wvec, float* __restrict__ part,
               int Ntot, float scaleAB)
{
    extern __shared__ char smem[];
    const uint32_t sb = smem_u32(smem);
    const int tid = threadIdx.x, lane = tid & 31, wid = tid >> 5;
    const int ntile = blockIdx.x, mtile = blockIdx.y;

    float* wvsh = (float*)(smem + WV_OFF);
    float* red  = (float*)(smem + RED_OFF);
    if (tid < 128) wvsh[tid] = wvec[ntile * NT + tid];

    // cp.async assignment: mat = tid>>7 (0:Aq1 1:Aq2 2:Bq1 3:Bq2), row = tid&127
    const int mat = tid >> 7;
    const int row = tid & 127;
    const char* gsrc;
    {
        const size_t arow = (size_t)(mtile * MT + row) * HID;
        const size_t brow = (size_t)(ntile * NT + row) * HID;
        gsrc = (mat == 0) ? Xq1 + arow :
               (mat == 1) ? Xq2 + arow :
               (mat == 2) ? Wq1 + brow : Wq2 + brow;
    }
    const uint32_t sdst = (uint32_t)(mat * VERB + row * ROWB);

    const int m_off = (wid & 3) * 32;
    const int n_off = (wid >> 2) * 32;
    const int lm_row  = lane & 15;
    const int lm_colb = (lane & 16) ? 16 : 0;

    int ahh[2][4][4], axx[2][4][4];
#pragma unroll
    for (int t = 0; t < 2; t++)
#pragma unroll
        for (int n = 0; n < 4; n++)
#pragma unroll
            for (int j = 0; j < 4; j++) { ahh[t][n][j] = 0; axx[t][n][j] = 0; }

#define ISSUE(ci)                                                  \
    do {                                                           \
        const uint32_t s0 = sb + ((ci) & 1) * STAGEB + sdst;       \
        const char* g0 = gsrc + (size_t)(ci) * 32;                 \
        CP16(s0, g0);                                              \
        CP16(s0 + 16, g0 + 16);                                    \
        CP_COMMIT();                                               \
    } while (0)

    ISSUE(0);

    for (int i = 0; i < NCHUNK; ++i) {
        asm volatile("cp.async.wait_group 0;" ::: "memory");
        __syncthreads();
        if (i + 1 < NCHUNK) ISSUE(i + 1);

        const uint32_t SA = sb + (i & 1) * STAGEB;          // Aq1
        const uint32_t SB = SA + 2 * VERB;                  // Bq1
        uint32_t af[2][4], bf[2][4];

        // ---- product 1: Aq1 x Bq1 -> hh ----
#pragma unroll
        for (int t = 0; t < 2; t++)
            ldsm4(af[t], SA + (uint32_t)((m_off + t * 16 + lm_row) * ROWB) + lm_colb);
#pragma unroll
        for (int g = 0; g < 2; g++)
            ldsm4(bf[g], SB + (uint32_t)((n_off + g * 16 + lm_row) * ROWB) + lm_colb);
#pragma unroll
        for (int t = 0; t < 2; t++)
#pragma unroll
            for (int n8 = 0; n8 < 4; n8++) {
                const int g = n8 >> 1, u = n8 & 1;
                imma(ahh[t][n8], af[t], bf[g][u], bf[g][u + 2]);
            }

        // ---- product 2: Aq1 x Bq2 -> cross ----
#pragma unroll
        for (int g = 0; g < 2; g++)
            ldsm4(bf[g], SB + VERB + (uint32_t)((n_off + g * 16 + lm_row) * ROWB) + lm_colb);
#pragma unroll
        for (int t = 0; t < 2; t++)
#pragma unroll
            for (int n8 = 0; n8 < 4; n8++) {
                const int g = n8 >> 1, u = n8 & 1;
                imma(axx[t][n8], af[t], bf[g][u], bf[g][u + 2]);
            }

        // ---- product 3: Aq2 x Bq1 -> cross ----
#pragma unroll
        for (int t = 0; t < 2; t++)
            ldsm4(af[t], SA + VERB + (uint32_t)((m_off + t * 16 + lm_row) * ROWB) + lm_colb);
#pragma unroll
        for (int g = 0; g < 2; g++)
            ldsm4(bf[g], SB + (uint32_t)((n_off + g * 16 + lm_row) * ROWB) + lm_colb);
#pragma unroll
        for (int t = 0; t < 2; t++)
#pragma unroll
            for (int n8 = 0; n8 < 4; n8++) {
                const int g = n8 >> 1, u = n8 & 1;
                imma(axx[t][n8], af[t], bf[g][u], bf[g][u + 2]);
            }
    }

    // epilogue: dequant + tanh + dot(wv) -> per-row partials
    float s_lo[2] = {0.f, 0.f}, s_hi[2] = {0.f, 0.f};
#pragma unroll
    for (int t = 0; t < 2; t++)
#pragma unroll
        for (int n8 = 0; n8 < 4; n8++) {
            const float w0 = wvsh[n_off + n8 * 8 + (lane & 3) * 2];
            const float w1 = wvsh[n_off + n8 * 8 + (lane & 3) * 2 + 1];
            float c0 = scaleAB * ((float)ahh[t][n8][0] + (float)axx[t][n8][0] * 0.0078125f);
            float c1 = scaleAB * ((float)ahh[t][n8][1] + (float)axx[t][n8][1] * 0.0078125f);
            float c2 = scaleAB * ((float)ahh[t][n8][2] + (float)axx[t][n8][2] * 0.0078125f);
            float c3 = scaleAB * ((float)ahh[t][n8][3] + (float)axx[t][n8][3] * 0.0078125f);
            s_lo[t] = fmaf(fast_tanh(c0), w0, s_lo[t]);
            s_lo[t] = fmaf(fast_tanh(c1), w1, s_lo[t]);
            s_hi[t] = fmaf(fast_tanh(c2), w0, s_hi[t]);
            s_hi[t] = fmaf(fast_tanh(c3), w1, s_hi[t]);
        }
#pragma unroll
    for (int o = 1; o <= 2; o <<= 1) {
#pragma unroll
        for (int t = 0; t < 2; t++) {
            s_lo[t] += __shfl_xor_sync(0xffffffffu, s_lo[t], o);
            s_hi[t] += __shfl_xor_sync(0xffffffffu, s_hi[t], o);
        }
    }
    __syncthreads();
    if ((lane & 3) == 0) {
        const int r = lane >> 2;
        float* rw = red + (wid >> 2) * 128;
#pragma unroll
        for (int t = 0; t < 2; t++) {
            rw[m_off + t * 16 + r]     = s_lo[t];
            rw[m_off + t * 16 + r + 8] = s_hi[t];
        }
    }
    __syncthreads();
    if (tid < 128)
        part[ntile * Ntot + mtile * MT + tid] =
            red[tid] + red[128 + tid] + red[256 + tid] + red[384 + tid];
}

// ---------------------------------------------------------------------------
__device__ __forceinline__ float warpRedMax(float v) {
#pragma unroll
    for (int o = 16; o > 0; o >>= 1) v = fmaxf(v, __shfl_xor_sync(0xffffffffu, v, o));
    return v;
}
__device__ __forceinline__ float warpRedSum(float v) {
#pragma unroll
    for (int o = 16; o > 0; o >>= 1) v += __shfl_xor_sync(0xffffffffu, v, o);
    return v;
}

__global__ void softmax_rows(const float* __restrict__ part, int N, int n,
                             float* __restrict__ w)
{
    __shared__ float sh[8];
    const int b = blockIdx.x, tid = threadIdx.x, base = b * n;

    float m = -1e30f;
    for (int i = tid; i < n; i += 256) {
        float x = 0.f;
#pragma unroll
        for (int c = 0; c < NCT; c++) x += part[c * N + base + i];
        w[base + i] = x;
        m = fmaxf(m, x);
    }
    m = warpRedMax(m);
    if ((tid & 31) == 0) sh[tid >> 5] = m;
    __syncthreads();
    float M = sh[0];
#pragma unroll
    for (int t = 1; t < 8; t++) M = fmaxf(M, sh[t]);

    float sum = 0.f;
    for (int i = tid; i < n; i += 256) {
        float e = expf(w[base + i] - M);
        w[base + i] = e;
        sum += e;
    }
    sum = warpRedSum(sum);
    __syncthreads();
    if ((tid & 31) == 0) sh[tid >> 5] = sum;
    __syncthreads();
    float S = 0.f;
#pragma unroll
    for (int t = 0; t < 8; t++) S += sh[t];
    const float inv = 1.f / S;
    for (int i = tid; i < n; i += 256) w[base + i] *= inv;
}

__global__ void wsum_kernel(const float* __restrict__ w, const float* __restrict__ X,
                            int n, float* __restrict__ out)
{
    const int b = blockIdx.x;
    const int h = blockIdx.y * blockDim.x + threadIdx.x;
    const float* xb = X + (size_t)b * n * HID + h;
    const float* wb = w + b * n;
    float acc = 0.f;
#pragma unroll 4
    for (int r = 0; r < n; r++)
        acc = fmaf(__ldg(&wb[r]), xb[(size_t)r * HID], acc);
    out[b * HID + h] = acc;
}

__global__ void broadcast_kernel(const float* __restrict__ u, const float* __restrict__ v,
                                 float4* __restrict__ out)
{
    const int i  = blockIdx.x * blockDim.x + threadIdx.x;
    const int b  = i >> 17;
    const int h4 = i & 255;
    const float4* u4 = (const float4*)u;
    const float4* v4 = (const float4*)v;
    out[i] = u4[b * 256 + h4];
    out[(BATCH * SEQ * HID / 4) + i] = v4[b * 256 + h4];
}

// ---------------------------------------------------------------------------
extern "C" void kernel_launch(void* const* d_in, const int* in_sizes, int n_in,
                              void* d_out, int out_size)
{
    const float* dns    = (const float*)d_in[0];
    const float* img    = (const float*)d_in[1];
    const float* W_i1   = (const float*)d_in[4];
    const float* w_att1 = (const float*)d_in[5];
    const float* W_d2   = (const float*)d_in[7];
    const float* w_att2 = (const float*)d_in[10];
    float* out = (float*)d_out;

    float *part1, *part2, *w1, *w2, *v, *u;
    cudaGetSymbolAddress((void**)&part1, g_part1);
    cudaGetSymbolAddress((void**)&part2, g_part2);
    cudaGetSymbolAddress((void**)&w1, g_w1);
    cudaGetSymbolAddress((void**)&w2, g_w2);
    cudaGetSymbolAddress((void**)&v, g_v);
    cudaGetSymbolAddress((void**)&u, g_u);

    char *dq1, *dq2, *iq1, *iq2, *wiq1, *wiq2, *wdq1, *wdq2;
    cudaGetSymbolAddress((void**)&dq1, g_dns_q1);
    cudaGetSymbolAddress((void**)&dq2, g_dns_q2);
    cudaGetSymbolAddress((void**)&iq1, g_img_q1);
    cudaGetSymbolAddress((void**)&iq2, g_img_q2);
    cudaGetSymbolAddress((void**)&wiq1, g_wi_q1);
    cudaGetSymbolAddress((void**)&wiq2, g_wi_q2);
    cudaGetSymbolAddress((void**)&wdq1, g_wd_q1);
    cudaGetSymbolAddress((void**)&wdq2, g_wd_q2);

    const float invDA = 127.f / QA_BOUND;
    const float invDW = 127.f / QW_BOUND;
    const float scaleAB = (QA_BOUND / 127.f) * (QW_BOUND / 127.f);

    cudaFuncSetAttribute(gemm_imma, cudaFuncAttributeMaxDynamicSharedMemorySize, SMEM_DYN);

    quantize<<<(BATCH * SEQ * HID / 16) / 256, 256>>>(dns, (uint32_t*)dq1, (uint32_t*)dq2, invDA);
    quantize<<<(BATCH * RIMG * HID / 16) / 256, 256>>>(img, (uint32_t*)iq1, (uint32_t*)iq2, invDA);
    quantize<<<(HID * HID / 16) / 256, 256>>>(W_i1, (uint32_t*)wiq1, (uint32_t*)wiq2, invDW);
    quantize<<<(HID * HID / 16) / 256, 256>>>(W_d2, (uint32_t*)wdq1, (uint32_t*)wdq2, invDW);

    gemm_imma<<<dim3(NCT, BATCH * RIMG / MT), 512, SMEM_DYN>>>(
        iq1, iq2, wiq1, wiq2, w_att1 + HID, part1, BATCH * RIMG, scaleAB);
    gemm_imma<<<dim3(NCT, BATCH * SEQ / MT), 512, SMEM_DYN>>>(
        dq1, dq2, wdq1, wdq2, w_att2 + HID, part2, BATCH * SEQ, scaleAB);

    softmax_rows<<<BATCH, 256>>>(part1, BATCH * RIMG, RIMG, w1);
    softmax_rows<<<BATCH, 256>>>(part2, BATCH * SEQ, SEQ, w2);

    wsum_kernel<<<dim3(BATCH, HID / 256), 256>>>(w1, img, RIMG, v);
    wsum_kernel<<<dim3(BATCH, HID / 256), 256>>>(w2, dns, SEQ, u);

    broadcast_kernel<<<(BATCH * SEQ * HID / 4) / 256, 256>>>(u, v, (float4*)out);
}

// round 8
// speedup vs baseline: 3.2242x; 3.2242x over previous
#include <cuda_runtime.h>
#include <cuda_fp16.h>
#include <math.h>
#include <stdint.h>

#define HID   1024
#define BATCH 32
#define SEQ   512
#define RIMG  196
#define NCT   8
#define MT    128
#define NT    128
#define KC    64                      // fp16 K per chunk (128 B per row)
#define NCHUNK (HID / KC)
#define ROWB  144                     // 128B data + 16B pad
#define VERB  (128 * ROWB)            // 18432 B per matrix
#define STAGEB (2 * VERB)             // A, B = 36864
#define WV_OFF  (2 * STAGEB)          // 73728
#define RED_OFF (WV_OFF + 512)
#define SMEM_DYN (RED_OFF + 1024 + 256)

// ---------------- scratch ----------------
__device__ float g_part1[NCT * BATCH * RIMG];
__device__ float g_part2[NCT * BATCH * SEQ];
__device__ float g_w1[BATCH * RIMG];
__device__ float g_w2[BATCH * SEQ];
__device__ float g_v[BATCH * HID];
__device__ float g_u[BATCH * HID];

__device__ __half g_dns_h[BATCH * SEQ * HID];
__device__ __half g_img_h[BATCH * RIMG * HID];
__device__ __half g_wi_h[HID * HID];
__device__ __half g_wd_h[HID * HID];

// ---------------- helpers ----------------
__device__ __forceinline__ uint32_t smem_u32(const void* p) {
    uint32_t a;
    asm("{ .reg .u64 t; cvta.to.shared.u64 t, %1; cvt.u32.u64 %0, t; }" : "=r"(a) : "l"(p));
    return a;
}
__device__ __forceinline__ void ldsm4(uint32_t* r, uint32_t addr) {
    asm volatile("ldmatrix.sync.aligned.m8n8.x4.shared.b16 {%0,%1,%2,%3}, [%4];"
                 : "=r"(r[0]), "=r"(r[1]), "=r"(r[2]), "=r"(r[3]) : "r"(addr));
}
__device__ __forceinline__ void mma16816(float* c, const uint32_t* a,
                                         uint32_t b0, uint32_t b1) {
    asm volatile(
        "mma.sync.aligned.m16n8k16.row.col.f32.f16.f16.f32 "
        "{%0,%1,%2,%3}, {%4,%5,%6,%7}, {%8,%9}, {%0,%1,%2,%3};"
        : "+f"(c[0]), "+f"(c[1]), "+f"(c[2]), "+f"(c[3])
        : "r"(a[0]), "r"(a[1]), "r"(a[2]), "r"(a[3]), "r"(b0), "r"(b1));
}
#define CP16(s, g) \
    asm volatile("cp.async.cg.shared.global [%0], [%1], 16;" :: "r"(s), "l"(g) : "memory")
#define CP_COMMIT() asm volatile("cp.async.commit_group;" ::: "memory")

__device__ __forceinline__ float fast_tanh(float x) {
    return 1.f - 2.f / (__expf(2.f * x) + 1.f);
}

// ---------------------------------------------------------------------------
// fp32 -> fp16 convert, 8 elems/thread
// ---------------------------------------------------------------------------
__global__ __launch_bounds__(256)
void tohalf(const float* __restrict__ in, __half* __restrict__ out)
{
    const int i = blockIdx.x * blockDim.x + threadIdx.x;
    const float4* p = (const float4*)in + (size_t)i * 2;
    float4 a = p[0], b = p[1];
    __half2 h0 = __floats2half2_rn(a.x, a.y);
    __half2 h1 = __floats2half2_rn(a.z, a.w);
    __half2 h2 = __floats2half2_rn(b.x, b.y);
    __half2 h3 = __floats2half2_rn(b.z, b.w);
    uint4 o;
    o.x = *reinterpret_cast<uint32_t*>(&h0);
    o.y = *reinterpret_cast<uint32_t*>(&h1);
    o.z = *reinterpret_cast<uint32_t*>(&h2);
    o.w = *reinterpret_cast<uint32_t*>(&h3);
    ((uint4*)out)[i] = o;
}

// ---------------------------------------------------------------------------
// single-product fp16 mma GEMM(X·Wᵀ) + tanh + dot(wvec) per 128-col tile.
// 256 threads, warp tile 32x64, 2-stage cp.async pipeline, occupancy 2.
// ---------------------------------------------------------------------------
__global__ __launch_bounds__(256, 2)
void gemm_h(const __half* __restrict__ X, const __half* __restrict__ W,
            const float* __restrict__ wvec, float* __restrict__ part, int Ntot)
{
    extern __shared__ char smem[];
    const uint32_t sb = smem_u32(smem);
    const int tid = threadIdx.x, lane = tid & 31, wid = tid >> 5;
    const int ntile = blockIdx.x, mtile = blockIdx.y;

    float* wvsh = (float*)(smem + WV_OFF);
    float* red  = (float*)(smem + RED_OFF);
    if (tid < 128) wvsh[tid] = wvec[ntile * NT + tid];

    const int row  = tid >> 1;
    const int half = tid & 1;
    const char* pA = (const char*)(X + (size_t)(mtile * MT + row) * HID) + half * 64;
    const char* pB = (const char*)(W + (size_t)(ntile * NT + row) * HID) + half * 64;
    const uint32_t st = (uint32_t)(row * ROWB + half * 64);

    const int m_off = (wid & 3) * 32;
    const int n_off = (wid >> 2) * 64;
    const int lm_row  = lane & 15;
    const int lm_colb = (lane & 16) ? 16 : 0;

    float acc[2][8][4];
#pragma unroll
    for (int t = 0; t < 2; t++)
#pragma unroll
        for (int n = 0; n < 8; n++)
#pragma unroll
            for (int j = 0; j < 4; j++) acc[t][n][j] = 0.f;

#define ISSUE(ci)                                                  \
    do {                                                           \
        const uint32_t s0 = sb + ((ci) & 1) * STAGEB + st;         \
        const char* gA = pA + (size_t)(ci) * 128;                  \
        const char* gB = pB + (size_t)(ci) * 128;                  \
        CP16(s0,      gA);                                         \
        CP16(s0 + 16, gA + 16);                                    \
        CP16(s0 + 32, gA + 32);                                    \
        CP16(s0 + 48, gA + 48);                                    \
        CP16(s0 + VERB,      gB);                                  \
        CP16(s0 + VERB + 16, gB + 16);                             \
        CP16(s0 + VERB + 32, gB + 32);                             \
        CP16(s0 + VERB + 48, gB + 48);                             \
        CP_COMMIT();                                               \
    } while (0)

    ISSUE(0);

    for (int i = 0; i < NCHUNK; ++i) {
        asm volatile("cp.async.wait_group 0;" ::: "memory");
        __syncthreads();
        if (i + 1 < NCHUNK) ISSUE(i + 1);

        const uint32_t SA = sb + (i & 1) * STAGEB;
        const uint32_t SB = SA + VERB;
#pragma unroll
        for (int ks = 0; ks < 4; ks++) {
            const uint32_t aoff = (uint32_t)(ks * 32 + lm_colb);
            uint32_t af[2][4], bf[4][4];
#pragma unroll
            for (int t = 0; t < 2; t++)
                ldsm4(af[t], SA + (uint32_t)((m_off + t * 16 + lm_row) * ROWB) + aoff);
#pragma unroll
            for (int q = 0; q < 4; q++)
                ldsm4(bf[q], SB + (uint32_t)((n_off + q * 16 + lm_row) * ROWB) + aoff);
#pragma unroll
            for (int t = 0; t < 2; t++)
#pragma unroll
                for (int n8 = 0; n8 < 8; n8++) {
                    const int q = n8 >> 1, u = n8 & 1;
                    mma16816(acc[t][n8], af[t], bf[q][u], bf[q][u + 2]);
                }
        }
    }

    // epilogue: tanh + dot(wv) -> per-row partials
    float s0[2] = {0.f, 0.f}, s1[2] = {0.f, 0.f};
#pragma unroll
    for (int t = 0; t < 2; t++)
#pragma unroll
        for (int n8 = 0; n8 < 8; n8++) {
            const float w0 = wvsh[n_off + n8 * 8 + (lane & 3) * 2];
            const float w1 = wvsh[n_off + n8 * 8 + (lane & 3) * 2 + 1];
            s0[t] = fmaf(fast_tanh(acc[t][n8][0]), w0, s0[t]);
            s0[t] = fmaf(fast_tanh(acc[t][n8][1]), w1, s0[t]);
            s1[t] = fmaf(fast_tanh(acc[t][n8][2]), w0, s1[t]);
            s1[t] = fmaf(fast_tanh(acc[t][n8][3]), w1, s1[t]);
        }
#pragma unroll
    for (int o = 1; o <= 2; o <<= 1) {
#pragma unroll
        for (int t = 0; t < 2; t++) {
            s0[t] += __shfl_xor_sync(0xffffffffu, s0[t], o);
            s1[t] += __shfl_xor_sync(0xffffffffu, s1[t], o);
        }
    }
    __syncthreads();
    if ((lane & 3) == 0) {
        const int r = lane >> 2;
        float* rw = red + (wid >> 2) * 128;
        rw[m_off + r]          = s0[0];
        rw[m_off + r + 8]      = s1[0];
        rw[m_off + 16 + r]     = s0[1];
        rw[m_off + 16 + r + 8] = s1[1];
    }
    __syncthreads();
    if (tid < 128)
        part[ntile * Ntot + mtile * MT + tid] = red[tid] + red[128 + tid];
}

// ---------------------------------------------------------------------------
__device__ __forceinline__ float warpRedMax(float v) {
#pragma unroll
    for (int o = 16; o > 0; o >>= 1) v = fmaxf(v, __shfl_xor_sync(0xffffffffu, v, o));
    return v;
}
__device__ __forceinline__ float warpRedSum(float v) {
#pragma unroll
    for (int o = 16; o > 0; o >>= 1) v += __shfl_xor_sync(0xffffffffu, v, o);
    return v;
}

__global__ void softmax_rows(const float* __restrict__ part, int N, int n,
                             float* __restrict__ w)
{
    __shared__ float sh[8];
    const int b = blockIdx.x, tid = threadIdx.x, base = b * n;

    float m = -1e30f;
    for (int i = tid; i < n; i += 256) {
        float x = 0.f;
#pragma unroll
        for (int c = 0; c < NCT; c++) x += part[c * N + base + i];
        w[base + i] = x;
        m = fmaxf(m, x);
    }
    m = warpRedMax(m);
    if ((tid & 31) == 0) sh[tid >> 5] = m;
    __syncthreads();
    float M = sh[0];
#pragma unroll
    for (int t = 1; t < 8; t++) M = fmaxf(M, sh[t]);

    float sum = 0.f;
    for (int i = tid; i < n; i += 256) {
        float e = expf(w[base + i] - M);
        w[base + i] = e;
        sum += e;
    }
    sum = warpRedSum(sum);
    __syncthreads();
    if ((tid & 31) == 0) sh[tid >> 5] = sum;
    __syncthreads();
    float S = 0.f;
#pragma unroll
    for (int t = 0; t < 8; t++) S += sh[t];
    const float inv = 1.f / S;
    for (int i = tid; i < n; i += 256) w[base + i] *= inv;
}

__global__ void wsum_kernel(const float* __restrict__ w, const float* __restrict__ X,
                            int n, float* __restrict__ out)
{
    const int b = blockIdx.x;
    const int h = blockIdx.y * blockDim.x + threadIdx.x;
    const float* xb = X + (size_t)b * n * HID + h;
    const float* wb = w + b * n;
    float acc = 0.f;
#pragma unroll 4
    for (int r = 0; r < n; r++)
        acc = fmaf(__ldg(&wb[r]), xb[(size_t)r * HID], acc);
    out[b * HID + h] = acc;
}

__global__ void broadcast_kernel(const float* __restrict__ u, const float* __restrict__ v,
                                 float4* __restrict__ out)
{
    const int i  = blockIdx.x * blockDim.x + threadIdx.x;
    const int b  = i >> 17;
    const int h4 = i & 255;
    const float4* u4 = (const float4*)u;
    const float4* v4 = (const float4*)v;
    out[i] = u4[b * 256 + h4];
    out[(BATCH * SEQ * HID / 4) + i] = v4[b * 256 + h4];
}

// ---------------------------------------------------------------------------
extern "C" void kernel_launch(void* const* d_in, const int* in_sizes, int n_in,
                              void* d_out, int out_size)
{
    const float* dns    = (const float*)d_in[0];
    const float* img    = (const float*)d_in[1];
    const float* W_i1   = (const float*)d_in[4];
    const float* w_att1 = (const float*)d_in[5];
    const float* W_d2   = (const float*)d_in[7];
    const float* w_att2 = (const float*)d_in[10];
    float* out = (float*)d_out;

    float *part1, *part2, *w1, *w2, *v, *u;
    cudaGetSymbolAddress((void**)&part1, g_part1);
    cudaGetSymbolAddress((void**)&part2, g_part2);
    cudaGetSymbolAddress((void**)&w1, g_w1);
    cudaGetSymbolAddress((void**)&w2, g_w2);
    cudaGetSymbolAddress((void**)&v, g_v);
    cudaGetSymbolAddress((void**)&u, g_u);

    __half *dns_h, *img_h, *wi_h, *wd_h;
    cudaGetSymbolAddress((void**)&dns_h, g_dns_h);
    cudaGetSymbolAddress((void**)&img_h, g_img_h);
    cudaGetSymbolAddress((void**)&wi_h, g_wi_h);
    cudaGetSymbolAddress((void**)&wd_h, g_wd_h);

    cudaFuncSetAttribute(gemm_h, cudaFuncAttributeMaxDynamicSharedMemorySize, SMEM_DYN);

    tohalf<<<(BATCH * SEQ * HID / 8) / 256, 256>>>(dns, dns_h);
    tohalf<<<(BATCH * RIMG * HID / 8) / 256, 256>>>(img, img_h);
    tohalf<<<(HID * HID / 8) / 256, 256>>>(W_i1, wi_h);
    tohalf<<<(HID * HID / 8) / 256, 256>>>(W_d2, wd_h);

    gemm_h<<<dim3(NCT, BATCH * RIMG / MT), 256, SMEM_DYN>>>(
        img_h, wi_h, w_att1 + HID, part1, BATCH * RIMG);
    gemm_h<<<dim3(NCT, BATCH * SEQ / MT), 256, SMEM_DYN>>>(
        dns_h, wd_h, w_att2 + HID, part2, BATCH * SEQ);

    softmax_rows<<<BATCH, 256>>>(part1, BATCH * RIMG, RIMG, w1);
    softmax_rows<<<BATCH, 256>>>(part2, BATCH * SEQ, SEQ, w2);

    wsum_kernel<<<dim3(BATCH, HID / 256), 256>>>(w1, img, RIMG, v);
    wsum_kernel<<<dim3(BATCH, HID / 256), 256>>>(w2, dns, SEQ, u);

    broadcast_kernel<<<(BATCH * SEQ * HID / 4) / 256, 256>>>(u, v, (float4*)out);
}

// round 9
// speedup vs baseline: 3.6289x; 1.1255x over previous
#include <cuda_runtime.h>
#include <cuda_fp16.h>
#include <math.h>
#include <stdint.h>

#define HID   1024
#define BATCH 32
#define SEQ   512
#define RIMG  196
#define NCT   8
#define MT    128
#define NT    128
#define KC    64
#define NCHUNK (HID / KC)
#define ROWB  144
#define VERB  (128 * ROWB)
#define STAGEB (2 * VERB)
#define WV_OFF  (2 * STAGEB)
#define RED_OFF (WV_OFF + 512)
#define SMEM_DYN (RED_OFF + 1024 + 256)

#define IMG_MT (BATCH * RIMG / MT)    // 49
#define DNS_MT (BATCH * SEQ / MT)     // 128

// ---------------- scratch ----------------
__device__ float g_part1[NCT * BATCH * RIMG];
__device__ float g_part2[NCT * BATCH * SEQ];
__device__ float g_w1[BATCH * RIMG];
__device__ float g_w2[BATCH * SEQ];
__device__ float g_v[BATCH * HID];
__device__ float g_u[BATCH * HID];

__device__ __half g_dns_h[BATCH * SEQ * HID];
__device__ __half g_img_h[BATCH * RIMG * HID];
__device__ __half g_wi_h[HID * HID];
__device__ __half g_wd_h[HID * HID];

// ---------------- helpers ----------------
__device__ __forceinline__ uint32_t smem_u32(const void* p) {
    uint32_t a;
    asm("{ .reg .u64 t; cvta.to.shared.u64 t, %1; cvt.u32.u64 %0, t; }" : "=r"(a) : "l"(p));
    return a;
}
__device__ __forceinline__ void ldsm4(uint32_t* r, uint32_t addr) {
    asm volatile("ldmatrix.sync.aligned.m8n8.x4.shared.b16 {%0,%1,%2,%3}, [%4];"
                 : "=r"(r[0]), "=r"(r[1]), "=r"(r[2]), "=r"(r[3]) : "r"(addr));
}
__device__ __forceinline__ void mma16816(float* c, const uint32_t* a,
                                         uint32_t b0, uint32_t b1) {
    asm volatile(
        "mma.sync.aligned.m16n8k16.row.col.f32.f16.f16.f32 "
        "{%0,%1,%2,%3}, {%4,%5,%6,%7}, {%8,%9}, {%0,%1,%2,%3};"
        : "+f"(c[0]), "+f"(c[1]), "+f"(c[2]), "+f"(c[3])
        : "r"(a[0]), "r"(a[1]), "r"(a[2]), "r"(a[3]), "r"(b0), "r"(b1));
}
#define CP16(s, g) \
    asm volatile("cp.async.cg.shared.global [%0], [%1], 16;" :: "r"(s), "l"(g) : "memory")
#define CP_COMMIT() asm volatile("cp.async.commit_group;" ::: "memory")

__device__ __forceinline__ float fast_tanh(float x) {
    return 1.f - 2.f / (__expf(2.f * x) + 1.f);
}

// ---------------------------------------------------------------------------
// fused fp32->fp16 convert for all 4 tensors (block-range dispatch)
// block handles 2048 elems (256 thr x 8)
// ---------------------------------------------------------------------------
#define NB_DNS (BATCH * SEQ * HID / 2048)    // 8192
#define NB_IMG (BATCH * RIMG * HID / 2048)   // 3136
#define NB_W   (HID * HID / 2048)            // 512
__global__ __launch_bounds__(256)
void tohalf4(const float* __restrict__ i0, __half* __restrict__ o0,
             const float* __restrict__ i1, __half* __restrict__ o1,
             const float* __restrict__ i2, __half* __restrict__ o2,
             const float* __restrict__ i3, __half* __restrict__ o3)
{
    const int b = blockIdx.x;
    const float* in; __half* out; int base;
    if (b < NB_DNS)                       { in = i0; out = o0; base = b; }
    else if (b < NB_DNS + NB_IMG)         { in = i1; out = o1; base = b - NB_DNS; }
    else if (b < NB_DNS + NB_IMG + NB_W)  { in = i2; out = o2; base = b - NB_DNS - NB_IMG; }
    else                                  { in = i3; out = o3; base = b - NB_DNS - NB_IMG - NB_W; }
    const int i = base * 256 + threadIdx.x;
    const float4* p = (const float4*)in + (size_t)i * 2;
    float4 a = p[0], c = p[1];
    __half2 h0 = __floats2half2_rn(a.x, a.y);
    __half2 h1 = __floats2half2_rn(a.z, a.w);
    __half2 h2 = __floats2half2_rn(c.x, c.y);
    __half2 h3 = __floats2half2_rn(c.z, c.w);
    uint4 o;
    o.x = *reinterpret_cast<uint32_t*>(&h0);
    o.y = *reinterpret_cast<uint32_t*>(&h1);
    o.z = *reinterpret_cast<uint32_t*>(&h2);
    o.w = *reinterpret_cast<uint32_t*>(&h3);
    ((uint4*)out)[i] = o;
}

// ---------------------------------------------------------------------------
// fused single-launch fp16 GEMM for BOTH score paths.
// grid = (NCT, DNS_MT + IMG_MT). y < DNS_MT -> dns path, else img path.
// ---------------------------------------------------------------------------
__global__ __launch_bounds__(256, 2)
void gemm_h2(const __half* __restrict__ Xd, const __half* __restrict__ Wd,
             const float* __restrict__ wvd, float* __restrict__ partd,
             const __half* __restrict__ Xi, const __half* __restrict__ Wi,
             const float* __restrict__ wvi, float* __restrict__ parti)
{
    extern __shared__ char smem[];
    const uint32_t sb = smem_u32(smem);
    const int tid = threadIdx.x, lane = tid & 31, wid = tid >> 5;
    const int ntile = blockIdx.x;

    const __half *X, *W;
    const float* wvec;
    float* part;
    int mtile, Ntot;
    if (blockIdx.y < DNS_MT) {
        X = Xd; W = Wd; wvec = wvd; part = partd;
        mtile = blockIdx.y; Ntot = BATCH * SEQ;
    } else {
        X = Xi; W = Wi; wvec = wvi; part = parti;
        mtile = blockIdx.y - DNS_MT; Ntot = BATCH * RIMG;
    }

    float* wvsh = (float*)(smem + WV_OFF);
    float* red  = (float*)(smem + RED_OFF);
    if (tid < 128) wvsh[tid] = wvec[ntile * NT + tid];

    const int row  = tid >> 1;
    const int half = tid & 1;
    const char* pA = (const char*)(X + (size_t)(mtile * MT + row) * HID) + half * 64;
    const char* pB = (const char*)(W + (size_t)(ntile * NT + row) * HID) + half * 64;
    const uint32_t st = (uint32_t)(row * ROWB + half * 64);

    const int m_off = (wid & 3) * 32;
    const int n_off = (wid >> 2) * 64;
    const int lm_row  = lane & 15;
    const int lm_colb = (lane & 16) ? 16 : 0;

    float acc[2][8][4];
#pragma unroll
    for (int t = 0; t < 2; t++)
#pragma unroll
        for (int n = 0; n < 8; n++)
#pragma unroll
            for (int j = 0; j < 4; j++) acc[t][n][j] = 0.f;

#define ISSUE(ci)                                                  \
    do {                                                           \
        const uint32_t s0 = sb + ((ci) & 1) * STAGEB + st;         \
        const char* gA = pA + (size_t)(ci) * 128;                  \
        const char* gB = pB + (size_t)(ci) * 128;                  \
        CP16(s0,      gA);                                         \
        CP16(s0 + 16, gA + 16);                                    \
        CP16(s0 + 32, gA + 32);                                    \
        CP16(s0 + 48, gA + 48);                                    \
        CP16(s0 + VERB,      gB);                                  \
        CP16(s0 + VERB + 16, gB + 16);                             \
        CP16(s0 + VERB + 32, gB + 32);                             \
        CP16(s0 + VERB + 48, gB + 48);                             \
        CP_COMMIT();                                               \
    } while (0)

    ISSUE(0);

    for (int i = 0; i < NCHUNK; ++i) {
        asm volatile("cp.async.wait_group 0;" ::: "memory");
        __syncthreads();
        if (i + 1 < NCHUNK) ISSUE(i + 1);

        const uint32_t SA = sb + (i & 1) * STAGEB;
        const uint32_t SB = SA + VERB;
#pragma unroll
        for (int ks = 0; ks < 4; ks++) {
            const uint32_t aoff = (uint32_t)(ks * 32 + lm_colb);
            uint32_t af[2][4], bf[4][4];
#pragma unroll
            for (int t = 0; t < 2; t++)
                ldsm4(af[t], SA + (uint32_t)((m_off + t * 16 + lm_row) * ROWB) + aoff);
#pragma unroll
            for (int q = 0; q < 4; q++)
                ldsm4(bf[q], SB + (uint32_t)((n_off + q * 16 + lm_row) * ROWB) + aoff);
#pragma unroll
            for (int t = 0; t < 2; t++)
#pragma unroll
                for (int n8 = 0; n8 < 8; n8++) {
                    const int q = n8 >> 1, u = n8 & 1;
                    mma16816(acc[t][n8], af[t], bf[q][u], bf[q][u + 2]);
                }
        }
    }

    // epilogue: tanh + dot(wv) -> per-row partials
    float s0[2] = {0.f, 0.f}, s1[2] = {0.f, 0.f};
#pragma unroll
    for (int t = 0; t < 2; t++)
#pragma unroll
        for (int n8 = 0; n8 < 8; n8++) {
            const float w0 = wvsh[n_off + n8 * 8 + (lane & 3) * 2];
            const float w1 = wvsh[n_off + n8 * 8 + (lane & 3) * 2 + 1];
            s0[t] = fmaf(fast_tanh(acc[t][n8][0]), w0, s0[t]);
            s0[t] = fmaf(fast_tanh(acc[t][n8][1]), w1, s0[t]);
            s1[t] = fmaf(fast_tanh(acc[t][n8][2]), w0, s1[t]);
            s1[t] = fmaf(fast_tanh(acc[t][n8][3]), w1, s1[t]);
        }
#pragma unroll
    for (int o = 1; o <= 2; o <<= 1) {
#pragma unroll
        for (int t = 0; t < 2; t++) {
            s0[t] += __shfl_xor_sync(0xffffffffu, s0[t], o);
            s1[t] += __shfl_xor_sync(0xffffffffu, s1[t], o);
        }
    }
    __syncthreads();
    if ((lane & 3) == 0) {
        const int r = lane >> 2;
        float* rw = red + (wid >> 2) * 128;
        rw[m_off + r]          = s0[0];
        rw[m_off + r + 8]      = s1[0];
        rw[m_off + 16 + r]     = s0[1];
        rw[m_off + 16 + r + 8] = s1[1];
    }
    __syncthreads();
    if (tid < 128)
        part[ntile * Ntot + mtile * MT + tid] = red[tid] + red[128 + tid];
}

// ---------------------------------------------------------------------------
__device__ __forceinline__ float warpRedMax(float v) {
#pragma unroll
    for (int o = 16; o > 0; o >>= 1) v = fmaxf(v, __shfl_xor_sync(0xffffffffu, v, o));
    return v;
}
__device__ __forceinline__ float warpRedSum(float v) {
#pragma unroll
    for (int o = 16; o > 0; o >>= 1) v += __shfl_xor_sync(0xffffffffu, v, o);
    return v;
}

// fused softmax for both paths: blocks 0-31 -> img (w1), 32-63 -> dns (w2)
__global__ void softmax2(const float* __restrict__ part1, float* __restrict__ w1out,
                         const float* __restrict__ part2, float* __restrict__ w2out)
{
    __shared__ float sh[8];
    const int blk = blockIdx.x, tid = threadIdx.x;
    const float* part;
    float* w;
    int b, n, N;
    if (blk < BATCH) { part = part1; w = w1out; b = blk; n = RIMG; N = BATCH * RIMG; }
    else             { part = part2; w = w2out; b = blk - BATCH; n = SEQ; N = BATCH * SEQ; }
    const int base = b * n;

    float m = -1e30f;
    for (int i = tid; i < n; i += 256) {
        float x = 0.f;
#pragma unroll
        for (int c = 0; c < NCT; c++) x += part[c * N + base + i];
        w[base + i] = x;
        m = fmaxf(m, x);
    }
    m = warpRedMax(m);
    if ((tid & 31) == 0) sh[tid >> 5] = m;
    __syncthreads();
    float M = sh[0];
#pragma unroll
    for (int t = 1; t < 8; t++) M = fmaxf(M, sh[t]);

    float sum = 0.f;
    for (int i = tid; i < n; i += 256) {
        float e = expf(w[base + i] - M);
        w[base + i] = e;
        sum += e;
    }
    sum = warpRedSum(sum);
    __syncthreads();
    if ((tid & 31) == 0) sh[tid >> 5] = sum;
    __syncthreads();
    float S = 0.f;
#pragma unroll
    for (int t = 0; t < 8; t++) S += sh[t];
    const float inv = 1.f / S;
    for (int i = tid; i < n; i += 256) w[base + i] *= inv;
}

// fused weighted-sum: grid (BATCH, HID/256, 2); z=0 img->v, z=1 dns->u
__global__ void wsum2(const float* __restrict__ w1, const float* __restrict__ img,
                      float* __restrict__ v,
                      const float* __restrict__ w2, const float* __restrict__ dns,
                      float* __restrict__ u)
{
    const int b = blockIdx.x;
    const int h = blockIdx.y * blockDim.x + threadIdx.x;
    const float* X; const float* w; float* out; int n;
    if (blockIdx.z == 0) { X = img; w = w1; out = v; n = RIMG; }
    else                 { X = dns; w = w2; out = u; n = SEQ; }
    const float* xb = X + (size_t)b * n * HID + h;
    const float* wb = w + b * n;
    float acc = 0.f;
#pragma unroll 4
    for (int r = 0; r < n; r++)
        acc = fmaf(__ldg(&wb[r]), xb[(size_t)r * HID], acc);
    out[b * HID + h] = acc;
}

__global__ void broadcast_kernel(const float* __restrict__ u, const float* __restrict__ v,
                                 float4* __restrict__ out)
{
    const int i  = blockIdx.x * blockDim.x + threadIdx.x;
    const int b  = i >> 17;
    const int h4 = i & 255;
    const float4* u4 = (const float4*)u;
    const float4* v4 = (const float4*)v;
    out[i] = u4[b * 256 + h4];
    out[(BATCH * SEQ * HID / 4) + i] = v4[b * 256 + h4];
}

// ---------------------------------------------------------------------------
extern "C" void kernel_launch(void* const* d_in, const int* in_sizes, int n_in,
                              void* d_out, int out_size)
{
    const float* dns    = (const float*)d_in[0];
    const float* img    = (const float*)d_in[1];
    const float* W_i1   = (const float*)d_in[4];
    const float* w_att1 = (const float*)d_in[5];
    const float* W_d2   = (const float*)d_in[7];
    const float* w_att2 = (const float*)d_in[10];
    float* out = (float*)d_out;

    float *part1, *part2, *w1, *w2, *v, *u;
    cudaGetSymbolAddress((void**)&part1, g_part1);
    cudaGetSymbolAddress((void**)&part2, g_part2);
    cudaGetSymbolAddress((void**)&w1, g_w1);
    cudaGetSymbolAddress((void**)&w2, g_w2);
    cudaGetSymbolAddress((void**)&v, g_v);
    cudaGetSymbolAddress((void**)&u, g_u);

    __half *dns_h, *img_h, *wi_h, *wd_h;
    cudaGetSymbolAddress((void**)&dns_h, g_dns_h);
    cudaGetSymbolAddress((void**)&img_h, g_img_h);
    cudaGetSymbolAddress((void**)&wi_h, g_wi_h);
    cudaGetSymbolAddress((void**)&wd_h, g_wd_h);

    cudaFuncSetAttribute(gemm_h2, cudaFuncAttributeMaxDynamicSharedMemorySize, SMEM_DYN);

    tohalf4<<<NB_DNS + NB_IMG + 2 * NB_W, 256>>>(dns, dns_h, img, img_h,
                                                 W_i1, wi_h, W_d2, wd_h);

    gemm_h2<<<dim3(NCT, DNS_MT + IMG_MT), 256, SMEM_DYN>>>(
        dns_h, wd_h, w_att2 + HID, part2,
        img_h, wi_h, w_att1 + HID, part1);

    softmax2<<<2 * BATCH, 256>>>(part1, w1, part2, w2);

    wsum2<<<dim3(BATCH, HID / 256, 2), 256>>>(w1, img, v, w2, dns, u);

    broadcast_kernel<<<(BATCH * SEQ * HID / 4) / 256, 256>>>(u, v, (float4*)out);
}

// round 10
// speedup vs baseline: 4.2724x; 1.1773x over previous
#include <cuda_runtime.h>
#include <cuda_fp16.h>
#include <math.h>
#include <stdint.h>

#define HID   1024
#define SEQ   512
#define RIMG  196
#define BATCH 32
#define NCT   8
#define MT    128
#define NT    128
#define KC    64
#define NCHUNK (HID / KC)
#define ROWB  144
#define VERB  (128 * ROWB)
#define STAGEB (2 * VERB)
#define WV_OFF  (2 * STAGEB)
#define RED_OFF (WV_OFF + 512)
#define SMEM_DYN (RED_OFF + 1024 + 256)

#define IMG_MT (BATCH * RIMG / MT)    // 49
#define DNS_MT (BATCH * SEQ / MT)     // 128

#define VSPLIT 4                      // img r-splits (196 = 4*49)
#define USPLIT 8                      // dns r-splits (512 = 8*64)

// ---------------- scratch ----------------
__device__ float g_part1[NCT * BATCH * RIMG];
__device__ float g_part2[NCT * BATCH * SEQ];
__device__ float g_w1[BATCH * RIMG];
__device__ float g_w2[BATCH * SEQ];
__device__ float g_v[BATCH * HID];
__device__ float g_u[BATCH * HID];
__device__ float g_vp[VSPLIT * BATCH * HID];
__device__ float g_up[USPLIT * BATCH * HID];

__device__ __half g_dns_h[BATCH * SEQ * HID];
__device__ __half g_img_h[BATCH * RIMG * HID];
__device__ __half g_wi_h[HID * HID];
__device__ __half g_wd_h[HID * HID];

// ---------------- helpers ----------------
__device__ __forceinline__ uint32_t smem_u32(const void* p) {
    uint32_t a;
    asm("{ .reg .u64 t; cvta.to.shared.u64 t, %1; cvt.u32.u64 %0, t; }" : "=r"(a) : "l"(p));
    return a;
}
__device__ __forceinline__ void ldsm4(uint32_t* r, uint32_t addr) {
    asm volatile("ldmatrix.sync.aligned.m8n8.x4.shared.b16 {%0,%1,%2,%3}, [%4];"
                 : "=r"(r[0]), "=r"(r[1]), "=r"(r[2]), "=r"(r[3]) : "r"(addr));
}
__device__ __forceinline__ void mma16816(float* c, const uint32_t* a,
                                         uint32_t b0, uint32_t b1) {
    asm volatile(
        "mma.sync.aligned.m16n8k16.row.col.f32.f16.f16.f32 "
        "{%0,%1,%2,%3}, {%4,%5,%6,%7}, {%8,%9}, {%0,%1,%2,%3};"
        : "+f"(c[0]), "+f"(c[1]), "+f"(c[2]), "+f"(c[3])
        : "r"(a[0]), "r"(a[1]), "r"(a[2]), "r"(a[3]), "r"(b0), "r"(b1));
}
#define CP16(s, g) \
    asm volatile("cp.async.cg.shared.global [%0], [%1], 16;" :: "r"(s), "l"(g) : "memory")
#define CP_COMMIT() asm volatile("cp.async.commit_group;" ::: "memory")

__device__ __forceinline__ float fast_tanh(float x) {
    return 1.f - 2.f / (__expf(2.f * x) + 1.f);
}

// ---------------------------------------------------------------------------
// fused fp32->fp16 convert for all 4 tensors
// ---------------------------------------------------------------------------
#define NB_DNS (BATCH * SEQ * HID / 2048)    // 8192
#define NB_IMG (BATCH * RIMG * HID / 2048)   // 3136
#define NB_W   (HID * HID / 2048)            // 512
__global__ __launch_bounds__(256)
void tohalf4(const float* __restrict__ i0, __half* __restrict__ o0,
             const float* __restrict__ i1, __half* __restrict__ o1,
             const float* __restrict__ i2, __half* __restrict__ o2,
             const float* __restrict__ i3, __half* __restrict__ o3)
{
    const int b = blockIdx.x;
    const float* in; __half* out; int base;
    if (b < NB_DNS)                       { in = i0; out = o0; base = b; }
    else if (b < NB_DNS + NB_IMG)         { in = i1; out = o1; base = b - NB_DNS; }
    else if (b < NB_DNS + NB_IMG + NB_W)  { in = i2; out = o2; base = b - NB_DNS - NB_IMG; }
    else                                  { in = i3; out = o3; base = b - NB_DNS - NB_IMG - NB_W; }
    const int i = base * 256 + threadIdx.x;
    const float4* p = (const float4*)in + (size_t)i * 2;
    float4 a = p[0], c = p[1];
    __half2 h0 = __floats2half2_rn(a.x, a.y);
    __half2 h1 = __floats2half2_rn(a.z, a.w);
    __half2 h2 = __floats2half2_rn(c.x, c.y);
    __half2 h3 = __floats2half2_rn(c.z, c.w);
    uint4 o;
    o.x = *reinterpret_cast<uint32_t*>(&h0);
    o.y = *reinterpret_cast<uint32_t*>(&h1);
    o.z = *reinterpret_cast<uint32_t*>(&h2);
    o.w = *reinterpret_cast<uint32_t*>(&h3);
    ((uint4*)out)[i] = o;
}

// ---------------------------------------------------------------------------
// fused single-launch fp16 GEMM for BOTH score paths.
// ---------------------------------------------------------------------------
__global__ __launch_bounds__(256, 2)
void gemm_h2(const __half* __restrict__ Xd, const __half* __restrict__ Wd,
             const float* __restrict__ wvd, float* __restrict__ partd,
             const __half* __restrict__ Xi, const __half* __restrict__ Wi,
             const float* __restrict__ wvi, float* __restrict__ parti)
{
    extern __shared__ char smem[];
    const uint32_t sb = smem_u32(smem);
    const int tid = threadIdx.x, lane = tid & 31, wid = tid >> 5;
    const int ntile = blockIdx.x;

    const __half *X, *W;
    const float* wvec;
    float* part;
    int mtile, Ntot;
    if (blockIdx.y < DNS_MT) {
        X = Xd; W = Wd; wvec = wvd; part = partd;
        mtile = blockIdx.y; Ntot = BATCH * SEQ;
    } else {
        X = Xi; W = Wi; wvec = wvi; part = parti;
        mtile = blockIdx.y - DNS_MT; Ntot = BATCH * RIMG;
    }

    float* wvsh = (float*)(smem + WV_OFF);
    float* red  = (float*)(smem + RED_OFF);
    if (tid < 128) wvsh[tid] = wvec[ntile * NT + tid];

    const int row  = tid >> 1;
    const int half = tid & 1;
    const char* pA = (const char*)(X + (size_t)(mtile * MT + row) * HID) + half * 64;
    const char* pB = (const char*)(W + (size_t)(ntile * NT + row) * HID) + half * 64;
    const uint32_t st = (uint32_t)(row * ROWB + half * 64);

    const int m_off = (wid & 3) * 32;
    const int n_off = (wid >> 2) * 64;
    const int lm_row  = lane & 15;
    const int lm_colb = (lane & 16) ? 16 : 0;

    float acc[2][8][4];
#pragma unroll
    for (int t = 0; t < 2; t++)
#pragma unroll
        for (int n = 0; n < 8; n++)
#pragma unroll
            for (int j = 0; j < 4; j++) acc[t][n][j] = 0.f;

#define ISSUE(ci)                                                  \
    do {                                                           \
        const uint32_t s0 = sb + ((ci) & 1) * STAGEB + st;         \
        const char* gA = pA + (size_t)(ci) * 128;                  \
        const char* gB = pB + (size_t)(ci) * 128;                  \
        CP16(s0,      gA);                                         \
        CP16(s0 + 16, gA + 16);                                    \
        CP16(s0 + 32, gA + 32);                                    \
        CP16(s0 + 48, gA + 48);                                    \
        CP16(s0 + VERB,      gB);                                  \
        CP16(s0 + VERB + 16, gB + 16);                             \
        CP16(s0 + VERB + 32, gB + 32);                             \
        CP16(s0 + VERB + 48, gB + 48);                             \
        CP_COMMIT();                                               \
    } while (0)

    ISSUE(0);

    for (int i = 0; i < NCHUNK; ++i) {
        asm volatile("cp.async.wait_group 0;" ::: "memory");
        __syncthreads();
        if (i + 1 < NCHUNK) ISSUE(i + 1);

        const uint32_t SA = sb + (i & 1) * STAGEB;
        const uint32_t SB = SA + VERB;
#pragma unroll
        for (int ks = 0; ks < 4; ks++) {
            const uint32_t aoff = (uint32_t)(ks * 32 + lm_colb);
            uint32_t af[2][4], bf[4][4];
#pragma unroll
            for (int t = 0; t < 2; t++)
                ldsm4(af[t], SA + (uint32_t)((m_off + t * 16 + lm_row) * ROWB) + aoff);
#pragma unroll
            for (int q = 0; q < 4; q++)
                ldsm4(bf[q], SB + (uint32_t)((n_off + q * 16 + lm_row) * ROWB) + aoff);
#pragma unroll
            for (int t = 0; t < 2; t++)
#pragma unroll
                for (int n8 = 0; n8 < 8; n8++) {
                    const int q = n8 >> 1, u = n8 & 1;
                    mma16816(acc[t][n8], af[t], bf[q][u], bf[q][u + 2]);
                }
        }
    }

    float s0[2] = {0.f, 0.f}, s1[2] = {0.f, 0.f};
#pragma unroll
    for (int t = 0; t < 2; t++)
#pragma unroll
        for (int n8 = 0; n8 < 8; n8++) {
            const float w0 = wvsh[n_off + n8 * 8 + (lane & 3) * 2];
            const float w1 = wvsh[n_off + n8 * 8 + (lane & 3) * 2 + 1];
            s0[t] = fmaf(fast_tanh(acc[t][n8][0]), w0, s0[t]);
            s0[t] = fmaf(fast_tanh(acc[t][n8][1]), w1, s0[t]);
            s1[t] = fmaf(fast_tanh(acc[t][n8][2]), w0, s1[t]);
            s1[t] = fmaf(fast_tanh(acc[t][n8][3]), w1, s1[t]);
        }
#pragma unroll
    for (int o = 1; o <= 2; o <<= 1) {
#pragma unroll
        for (int t = 0; t < 2; t++) {
            s0[t] += __shfl_xor_sync(0xffffffffu, s0[t], o);
            s1[t] += __shfl_xor_sync(0xffffffffu, s1[t], o);
        }
    }
    __syncthreads();
    if ((lane & 3) == 0) {
        const int r = lane >> 2;
        float* rw = red + (wid >> 2) * 128;
        rw[m_off + r]          = s0[0];
        rw[m_off + r + 8]      = s1[0];
        rw[m_off + 16 + r]     = s0[1];
        rw[m_off + 16 + r + 8] = s1[1];
    }
    __syncthreads();
    if (tid < 128)
        part[ntile * Ntot + mtile * MT + tid] = red[tid] + red[128 + tid];
}

// ---------------------------------------------------------------------------
__device__ __forceinline__ float warpRedMax(float v) {
#pragma unroll
    for (int o = 16; o > 0; o >>= 1) v = fmaxf(v, __shfl_xor_sync(0xffffffffu, v, o));
    return v;
}
__device__ __forceinline__ float warpRedSum(float v) {
#pragma unroll
    for (int o = 16; o > 0; o >>= 1) v += __shfl_xor_sync(0xffffffffu, v, o);
    return v;
}

__global__ void softmax2(const float* __restrict__ part1, float* __restrict__ w1out,
                         const float* __restrict__ part2, float* __restrict__ w2out)
{
    __shared__ float sh[8];
    const int blk = blockIdx.x, tid = threadIdx.x;
    const float* part;
    float* w;
    int b, n, N;
    if (blk < BATCH) { part = part1; w = w1out; b = blk; n = RIMG; N = BATCH * RIMG; }
    else             { part = part2; w = w2out; b = blk - BATCH; n = SEQ; N = BATCH * SEQ; }
    const int base = b * n;

    float m = -1e30f;
    for (int i = tid; i < n; i += 256) {
        float x = 0.f;
#pragma unroll
        for (int c = 0; c < NCT; c++) x += part[c * N + base + i];
        w[base + i] = x;
        m = fmaxf(m, x);
    }
    m = warpRedMax(m);
    if ((tid & 31) == 0) sh[tid >> 5] = m;
    __syncthreads();
    float M = sh[0];
#pragma unroll
    for (int t = 1; t < 8; t++) M = fmaxf(M, sh[t]);

    float sum = 0.f;
    for (int i = tid; i < n; i += 256) {
        float e = expf(w[base + i] - M);
        w[base + i] = e;
        sum += e;
    }
    sum = warpRedSum(sum);
    __syncthreads();
    if ((tid & 31) == 0) sh[tid >> 5] = sum;
    __syncthreads();
    float S = 0.f;
#pragma unroll
    for (int t = 0; t < 8; t++) S += sh[t];
    const float inv = 1.f / S;
    for (int i = tid; i < n; i += 256) w[base + i] *= inv;
}

// ---------------------------------------------------------------------------
// split-r weighted sum partials: grid (BATCH, VSPLIT + USPLIT), 256 threads.
// y < VSPLIT: img rows chunk (49 rows) -> vp[y]; else dns chunk (64) -> up[y-4].
// thread t covers h = t*4..t*4+3 (float4, coalesced).
// ---------------------------------------------------------------------------
__global__ __launch_bounds__(256)
void wsum_part(const float* __restrict__ w1, const float* __restrict__ img,
               const float* __restrict__ w2, const float* __restrict__ dns,
               float* __restrict__ vp, float* __restrict__ up)
{
    const int b = blockIdx.x, y = blockIdx.y, t = threadIdx.x;
    const float* X; const float* w; float* outp; int r0, rn, n;
    if (y < VSPLIT) {
        X = img; w = w1; outp = vp + (size_t)y * BATCH * HID;
        r0 = y * (RIMG / VSPLIT); rn = RIMG / VSPLIT; n = RIMG;
    } else {
        const int s = y - VSPLIT;
        X = dns; w = w2; outp = up + (size_t)s * BATCH * HID;
        r0 = s * (SEQ / USPLIT); rn = SEQ / USPLIT; n = SEQ;
    }
    const float4* xb = (const float4*)(X + (size_t)b * n * HID) + (size_t)r0 * 256 + t;
    const float*  wb = w + b * n + r0;

    float4 acc = make_float4(0.f, 0.f, 0.f, 0.f);
#pragma unroll 4
    for (int r = 0; r < rn; r++) {
        const float wr = __ldg(&wb[r]);
        const float4 x = __ldg(&xb[(size_t)r * 256]);
        acc.x = fmaf(wr, x.x, acc.x);
        acc.y = fmaf(wr, x.y, acc.y);
        acc.z = fmaf(wr, x.z, acc.z);
        acc.w = fmaf(wr, x.w, acc.w);
    }
    ((float4*)(outp + b * HID))[t] = acc;
}

// reduce partials -> u, v. grid BATCH, 256 threads (one float4 each).
__global__ __launch_bounds__(256)
void reduce_uv(const float* __restrict__ vp, const float* __restrict__ up,
               float* __restrict__ v, float* __restrict__ u)
{
    const int b = blockIdx.x, t = threadIdx.x;
    float4 sv = make_float4(0.f, 0.f, 0.f, 0.f);
#pragma unroll
    for (int s = 0; s < VSPLIT; s++) {
        float4 x = ((const float4*)(vp + (size_t)s * BATCH * HID + b * HID))[t];
        sv.x += x.x; sv.y += x.y; sv.z += x.z; sv.w += x.w;
    }
    float4 su = make_float4(0.f, 0.f, 0.f, 0.f);
#pragma unroll
    for (int s = 0; s < USPLIT; s++) {
        float4 x = ((const float4*)(up + (size_t)s * BATCH * HID + b * HID))[t];
        su.x += x.x; su.y += x.y; su.z += x.z; su.w += x.w;
    }
    ((float4*)(v + b * HID))[t] = sv;
    ((float4*)(u + b * HID))[t] = su;
}

__global__ void broadcast_kernel(const float* __restrict__ u, const float* __restrict__ v,
                                 float4* __restrict__ out)
{
    const int i  = blockIdx.x * blockDim.x + threadIdx.x;
    const int b  = i >> 17;
    const int h4 = i & 255;
    const float4* u4 = (const float4*)u;
    const float4* v4 = (const float4*)v;
    out[i] = u4[b * 256 + h4];
    out[(BATCH * SEQ * HID / 4) + i] = v4[b * 256 + h4];
}

// ---------------------------------------------------------------------------
extern "C" void kernel_launch(void* const* d_in, const int* in_sizes, int n_in,
                              void* d_out, int out_size)
{
    const float* dns    = (const float*)d_in[0];
    const float* img    = (const float*)d_in[1];
    const float* W_i1   = (const float*)d_in[4];
    const float* w_att1 = (const float*)d_in[5];
    const float* W_d2   = (const float*)d_in[7];
    const float* w_att2 = (const float*)d_in[10];
    float* out = (float*)d_out;

    float *part1, *part2, *w1, *w2, *v, *u, *vp, *up;
    cudaGetSymbolAddress((void**)&part1, g_part1);
    cudaGetSymbolAddress((void**)&part2, g_part2);
    cudaGetSymbolAddress((void**)&w1, g_w1);
    cudaGetSymbolAddress((void**)&w2, g_w2);
    cudaGetSymbolAddress((void**)&v, g_v);
    cudaGetSymbolAddress((void**)&u, g_u);
    cudaGetSymbolAddress((void**)&vp, g_vp);
    cudaGetSymbolAddress((void**)&up, g_up);

    __half *dns_h, *img_h, *wi_h, *wd_h;
    cudaGetSymbolAddress((void**)&dns_h, g_dns_h);
    cudaGetSymbolAddress((void**)&img_h, g_img_h);
    cudaGetSymbolAddress((void**)&wi_h, g_wi_h);
    cudaGetSymbolAddress((void**)&wd_h, g_wd_h);

    cudaFuncSetAttribute(gemm_h2, cudaFuncAttributeMaxDynamicSharedMemorySize, SMEM_DYN);

    tohalf4<<<NB_DNS + NB_IMG + 2 * NB_W, 256>>>(dns, dns_h, img, img_h,
                                                 W_i1, wi_h, W_d2, wd_h);

    gemm_h2<<<dim3(NCT, DNS_MT + IMG_MT), 256, SMEM_DYN>>>(
        dns_h, wd_h, w_att2 + HID, part2,
        img_h, wi_h, w_att1 + HID, part1);

    softmax2<<<2 * BATCH, 256>>>(part1, w1, part2, w2);

    wsum_part<<<dim3(BATCH, VSPLIT + USPLIT), 256>>>(w1, img, w2, dns, vp, up);
    reduce_uv<<<BATCH, 256>>>(vp, up, v, u);

    broadcast_kernel<<<(BATCH * SEQ * HID / 4) / 256, 256>>>(u, v, (float4*)out);
}

// round 11
// speedup vs baseline: 4.3751x; 1.0240x over previous
#include <cuda_runtime.h>
#include <cuda_fp16.h>
#include <math.h>
#include <stdint.h>

#define HID   1024
#define SEQ   512
#define RIMG  196
#define BATCH 32
#define NCT   8
#define MT    128
#define NT    128
#define KC    64
#define NCHUNK (HID / KC)
#define ROWB  144
#define VERB  (128 * ROWB)
#define STAGEB (2 * VERB)
#define WV_OFF  (2 * STAGEB)
#define RED_OFF (WV_OFF + 512)
#define SMEM_DYN (RED_OFF + 1024 + 256)

#define IMG_MT (BATCH * RIMG / MT)    // 49
#define DNS_MT (BATCH * SEQ / MT)     // 128

#define VSPLIT 7                      // img r-splits (196 = 7*28)
#define USPLIT 16                     // dns r-splits (512 = 16*32)

// ---------------- scratch ----------------
__device__ float g_part1[NCT * BATCH * RIMG];
__device__ float g_part2[NCT * BATCH * SEQ];
__device__ float g_v[BATCH * HID];
__device__ float g_u[BATCH * HID];
__device__ float g_vp[VSPLIT * BATCH * HID];
__device__ float g_up[USPLIT * BATCH * HID];

__device__ __half g_dns_h[BATCH * SEQ * HID];
__device__ __half g_img_h[BATCH * RIMG * HID];
__device__ __half g_wi_h[HID * HID];
__device__ __half g_wd_h[HID * HID];

// ---------------- helpers ----------------
__device__ __forceinline__ uint32_t smem_u32(const void* p) {
    uint32_t a;
    asm("{ .reg .u64 t; cvta.to.shared.u64 t, %1; cvt.u32.u64 %0, t; }" : "=r"(a) : "l"(p));
    return a;
}
__device__ __forceinline__ void ldsm4(uint32_t* r, uint32_t addr) {
    asm volatile("ldmatrix.sync.aligned.m8n8.x4.shared.b16 {%0,%1,%2,%3}, [%4];"
                 : "=r"(r[0]), "=r"(r[1]), "=r"(r[2]), "=r"(r[3]) : "r"(addr));
}
__device__ __forceinline__ void mma16816(float* c, const uint32_t* a,
                                         uint32_t b0, uint32_t b1) {
    asm volatile(
        "mma.sync.aligned.m16n8k16.row.col.f32.f16.f16.f32 "
        "{%0,%1,%2,%3}, {%4,%5,%6,%7}, {%8,%9}, {%0,%1,%2,%3};"
        : "+f"(c[0]), "+f"(c[1]), "+f"(c[2]), "+f"(c[3])
        : "r"(a[0]), "r"(a[1]), "r"(a[2]), "r"(a[3]), "r"(b0), "r"(b1));
}
#define CP16(s, g) \
    asm volatile("cp.async.cg.shared.global [%0], [%1], 16;" :: "r"(s), "l"(g) : "memory")
#define CP_COMMIT() asm volatile("cp.async.commit_group;" ::: "memory")

__device__ __forceinline__ float fast_tanh(float x) {
    return 1.f - 2.f / (__expf(2.f * x) + 1.f);
}
__device__ __forceinline__ float warpRedMax(float v) {
#pragma unroll
    for (int o = 16; o > 0; o >>= 1) v = fmaxf(v, __shfl_xor_sync(0xffffffffu, v, o));
    return v;
}
__device__ __forceinline__ float warpRedSum(float v) {
#pragma unroll
    for (int o = 16; o > 0; o >>= 1) v += __shfl_xor_sync(0xffffffffu, v, o);
    return v;
}

// ---------------------------------------------------------------------------
// fused fp32->fp16 convert, 16 floats/thread (MLP 4)
// ---------------------------------------------------------------------------
#define NB_DNS (BATCH * SEQ * HID / 4096)    // 4096
#define NB_IMG (BATCH * RIMG * HID / 4096)   // 1568
#define NB_W   (HID * HID / 4096)            // 256
__global__ __launch_bounds__(256)
void tohalf4(const float* __restrict__ i0, __half* __restrict__ o0,
             const float* __restrict__ i1, __half* __restrict__ o1,
             const float* __restrict__ i2, __half* __restrict__ o2,
             const float* __restrict__ i3, __half* __restrict__ o3)
{
    const int b = blockIdx.x;
    const float* in; __half* out; int base;
    if (b < NB_DNS)                       { in = i0; out = o0; base = b; }
    else if (b < NB_DNS + NB_IMG)         { in = i1; out = o1; base = b - NB_DNS; }
    else if (b < NB_DNS + NB_IMG + NB_W)  { in = i2; out = o2; base = b - NB_DNS - NB_IMG; }
    else                                  { in = i3; out = o3; base = b - NB_DNS - NB_IMG - NB_W; }
    const int i = base * 256 + threadIdx.x;       // 16-float unit index
    const float4* p = (const float4*)in + (size_t)i * 4;
    float4 f[4];
#pragma unroll
    for (int j = 0; j < 4; j++) f[j] = __ldg(p + j);
    uint4* o = (uint4*)out + (size_t)i * 2;
#pragma unroll
    for (int half2grp = 0; half2grp < 2; half2grp++) {
        float4 a = f[half2grp * 2], c = f[half2grp * 2 + 1];
        __half2 h0 = __floats2half2_rn(a.x, a.y);
        __half2 h1 = __floats2half2_rn(a.z, a.w);
        __half2 h2 = __floats2half2_rn(c.x, c.y);
        __half2 h3 = __floats2half2_rn(c.z, c.w);
        uint4 w;
        w.x = *reinterpret_cast<uint32_t*>(&h0);
        w.y = *reinterpret_cast<uint32_t*>(&h1);
        w.z = *reinterpret_cast<uint32_t*>(&h2);
        w.w = *reinterpret_cast<uint32_t*>(&h3);
        o[half2grp] = w;
    }
}

// ---------------------------------------------------------------------------
// fused single-launch fp16 GEMM for BOTH score paths (unchanged from R9/R10).
// ---------------------------------------------------------------------------
__global__ __launch_bounds__(256, 2)
void gemm_h2(const __half* __restrict__ Xd, const __half* __restrict__ Wd,
             const float* __restrict__ wvd, float* __restrict__ partd,
             const __half* __restrict__ Xi, const __half* __restrict__ Wi,
             const float* __restrict__ wvi, float* __restrict__ parti)
{
    extern __shared__ char smem[];
    const uint32_t sb = smem_u32(smem);
    const int tid = threadIdx.x, lane = tid & 31, wid = tid >> 5;
    const int ntile = blockIdx.x;

    const __half *X, *W;
    const float* wvec;
    float* part;
    int mtile, Ntot;
    if (blockIdx.y < DNS_MT) {
        X = Xd; W = Wd; wvec = wvd; part = partd;
        mtile = blockIdx.y; Ntot = BATCH * SEQ;
    } else {
        X = Xi; W = Wi; wvec = wvi; part = parti;
        mtile = blockIdx.y - DNS_MT; Ntot = BATCH * RIMG;
    }

    float* wvsh = (float*)(smem + WV_OFF);
    float* red  = (float*)(smem + RED_OFF);
    if (tid < 128) wvsh[tid] = wvec[ntile * NT + tid];

    const int row  = tid >> 1;
    const int half = tid & 1;
    const char* pA = (const char*)(X + (size_t)(mtile * MT + row) * HID) + half * 64;
    const char* pB = (const char*)(W + (size_t)(ntile * NT + row) * HID) + half * 64;
    const uint32_t st = (uint32_t)(row * ROWB + half * 64);

    const int m_off = (wid & 3) * 32;
    const int n_off = (wid >> 2) * 64;
    const int lm_row  = lane & 15;
    const int lm_colb = (lane & 16) ? 16 : 0;

    float acc[2][8][4];
#pragma unroll
    for (int t = 0; t < 2; t++)
#pragma unroll
        for (int n = 0; n < 8; n++)
#pragma unroll
            for (int j = 0; j < 4; j++) acc[t][n][j] = 0.f;

#define ISSUE(ci)                                                  \
    do {                                                           \
        const uint32_t s0 = sb + ((ci) & 1) * STAGEB + st;         \
        const char* gA = pA + (size_t)(ci) * 128;                  \
        const char* gB = pB + (size_t)(ci) * 128;                  \
        CP16(s0,      gA);                                         \
        CP16(s0 + 16, gA + 16);                                    \
        CP16(s0 + 32, gA + 32);                                    \
        CP16(s0 + 48, gA + 48);                                    \
        CP16(s0 + VERB,      gB);                                  \
        CP16(s0 + VERB + 16, gB + 16);                             \
        CP16(s0 + VERB + 32, gB + 32);                             \
        CP16(s0 + VERB + 48, gB + 48);                             \
        CP_COMMIT();                                               \
    } while (0)

    ISSUE(0);

    for (int i = 0; i < NCHUNK; ++i) {
        asm volatile("cp.async.wait_group 0;" ::: "memory");
        __syncthreads();
        if (i + 1 < NCHUNK) ISSUE(i + 1);

        const uint32_t SA = sb + (i & 1) * STAGEB;
        const uint32_t SB = SA + VERB;
#pragma unroll
        for (int ks = 0; ks < 4; ks++) {
            const uint32_t aoff = (uint32_t)(ks * 32 + lm_colb);
            uint32_t af[2][4], bf[4][4];
#pragma unroll
            for (int t = 0; t < 2; t++)
                ldsm4(af[t], SA + (uint32_t)((m_off + t * 16 + lm_row) * ROWB) + aoff);
#pragma unroll
            for (int q = 0; q < 4; q++)
                ldsm4(bf[q], SB + (uint32_t)((n_off + q * 16 + lm_row) * ROWB) + aoff);
#pragma unroll
            for (int t = 0; t < 2; t++)
#pragma unroll
                for (int n8 = 0; n8 < 8; n8++) {
                    const int q = n8 >> 1, u = n8 & 1;
                    mma16816(acc[t][n8], af[t], bf[q][u], bf[q][u + 2]);
                }
        }
    }

    float s0[2] = {0.f, 0.f}, s1[2] = {0.f, 0.f};
#pragma unroll
    for (int t = 0; t < 2; t++)
#pragma unroll
        for (int n8 = 0; n8 < 8; n8++) {
            const float w0 = wvsh[n_off + n8 * 8 + (lane & 3) * 2];
            const float w1 = wvsh[n_off + n8 * 8 + (lane & 3) * 2 + 1];
            s0[t] = fmaf(fast_tanh(acc[t][n8][0]), w0, s0[t]);
            s0[t] = fmaf(fast_tanh(acc[t][n8][1]), w1, s0[t]);
            s1[t] = fmaf(fast_tanh(acc[t][n8][2]), w0, s1[t]);
            s1[t] = fmaf(fast_tanh(acc[t][n8][3]), w1, s1[t]);
        }
#pragma unroll
    for (int o = 1; o <= 2; o <<= 1) {
#pragma unroll
        for (int t = 0; t < 2; t++) {
            s0[t] += __shfl_xor_sync(0xffffffffu, s0[t], o);
            s1[t] += __shfl_xor_sync(0xffffffffu, s1[t], o);
        }
    }
    __syncthreads();
    if ((lane & 3) == 0) {
        const int r = lane >> 2;
        float* rw = red + (wid >> 2) * 128;
        rw[m_off + r]          = s0[0];
        rw[m_off + r + 8]      = s1[0];
        rw[m_off + 16 + r]     = s0[1];
        rw[m_off + 16 + r + 8] = s1[1];
    }
    __syncthreads();
    if (tid < 128)
        part[ntile * Ntot + mtile * MT + tid] = red[tid] + red[128 + tid];
}

// ---------------------------------------------------------------------------
// fused softmax + split-r weighted sum.
// grid (BATCH, VSPLIT + USPLIT), 256 threads. Each block recomputes its
// batch row's softmax weights into smem (deterministic, identical in every
// block), then reduces its r-chunk of X into a partial output row.
// ---------------------------------------------------------------------------
__global__ __launch_bounds__(256)
void wsum_sm(const float* __restrict__ part1, const float* __restrict__ img,
             const float* __restrict__ part2, const float* __restrict__ dns,
             float* __restrict__ vp, float* __restrict__ up)
{
    __shared__ float ws[SEQ];
    __shared__ float sh[8];
    const int b = blockIdx.x, y = blockIdx.y, t = threadIdx.x;

    const float* part; const float* X; float* outp;
    int r0, rn, n, N;
    if (y < VSPLIT) {
        part = part1; X = img; outp = vp + (size_t)y * BATCH * HID;
        r0 = y * (RIMG / VSPLIT); rn = RIMG / VSPLIT; n = RIMG; N = BATCH * RIMG;
    } else {
        const int s = y - VSPLIT;
        part = part2; X = dns; outp = up + (size_t)s * BATCH * HID;
        r0 = s * (SEQ / USPLIT); rn = SEQ / USPLIT; n = SEQ; N = BATCH * SEQ;
    }
    const int base = b * n;

    // --- softmax into smem ---
    float m = -1e30f;
    for (int i = t; i < n; i += 256) {
        float x = 0.f;
#pragma unroll
        for (int c = 0; c < NCT; c++) x += part[c * N + base + i];
        ws[i] = x;
        m = fmaxf(m, x);
    }
    m = warpRedMax(m);
    if ((t & 31) == 0) sh[t >> 5] = m;
    __syncthreads();
    float M = sh[0];
#pragma unroll
    for (int q = 1; q < 8; q++) M = fmaxf(M, sh[q]);

    float sum = 0.f;
    for (int i = t; i < n; i += 256) {
        float e = expf(ws[i] - M);
        ws[i] = e;
        sum += e;
    }
    sum = warpRedSum(sum);
    __syncthreads();
    if ((t & 31) == 0) sh[t >> 5] = sum;
    __syncthreads();
    float S = 0.f;
#pragma unroll
    for (int q = 0; q < 8; q++) S += sh[q];
    const float inv = 1.f / S;
    __syncthreads();   // ws fully written

    // --- weighted sum over r-chunk ---
    const float4* xb = (const float4*)(X + (size_t)b * n * HID) + (size_t)r0 * 256 + t;
    float4 acc = make_float4(0.f, 0.f, 0.f, 0.f);
#pragma unroll 4
    for (int r = 0; r < rn; r++) {
        const float wr = ws[r0 + r];
        const float4 x = __ldg(&xb[(size_t)r * 256]);
        acc.x = fmaf(wr, x.x, acc.x);
        acc.y = fmaf(wr, x.y, acc.y);
        acc.z = fmaf(wr, x.z, acc.z);
        acc.w = fmaf(wr, x.w, acc.w);
    }
    acc.x *= inv; acc.y *= inv; acc.z *= inv; acc.w *= inv;
    ((float4*)(outp + b * HID))[t] = acc;
}

// reduce partials -> u, v. grid BATCH, 256 threads (one float4 each).
__global__ __launch_bounds__(256)
void reduce_uv(const float* __restrict__ vp, const float* __restrict__ up,
               float* __restrict__ v, float* __restrict__ u)
{
    const int b = blockIdx.x, t = threadIdx.x;
    float4 sv = make_float4(0.f, 0.f, 0.f, 0.f);
#pragma unroll
    for (int s = 0; s < VSPLIT; s++) {
        float4 x = ((const float4*)(vp + (size_t)s * BATCH * HID + b * HID))[t];
        sv.x += x.x; sv.y += x.y; sv.z += x.z; sv.w += x.w;
    }
    float4 su = make_float4(0.f, 0.f, 0.f, 0.f);
#pragma unroll
    for (int s = 0; s < USPLIT; s++) {
        float4 x = ((const float4*)(up + (size_t)s * BATCH * HID + b * HID))[t];
        su.x += x.x; su.y += x.y; su.z += x.z; su.w += x.w;
    }
    ((float4*)(v + b * HID))[t] = sv;
    ((float4*)(u + b * HID))[t] = su;
}

__global__ void broadcast_kernel(const float* __restrict__ u, const float* __restrict__ v,
                                 float4* __restrict__ out)
{
    const int i  = blockIdx.x * blockDim.x + threadIdx.x;
    const int b  = i >> 17;
    const int h4 = i & 255;
    const float4* u4 = (const float4*)u;
    const float4* v4 = (const float4*)v;
    out[i] = u4[b * 256 + h4];
    out[(BATCH * SEQ * HID / 4) + i] = v4[b * 256 + h4];
}

// ---------------------------------------------------------------------------
extern "C" void kernel_launch(void* const* d_in, const int* in_sizes, int n_in,
                              void* d_out, int out_size)
{
    const float* dns    = (const float*)d_in[0];
    const float* img    = (const float*)d_in[1];
    const float* W_i1   = (const float*)d_in[4];
    const float* w_att1 = (const float*)d_in[5];
    const float* W_d2   = (const float*)d_in[7];
    const float* w_att2 = (const float*)d_in[10];
    float* out = (float*)d_out;

    float *part1, *part2, *v, *u, *vp, *up;
    cudaGetSymbolAddress((void**)&part1, g_part1);
    cudaGetSymbolAddress((void**)&part2, g_part2);
    cudaGetSymbolAddress((void**)&v, g_v);
    cudaGetSymbolAddress((void**)&u, g_u);
    cudaGetSymbolAddress((void**)&vp, g_vp);
    cudaGetSymbolAddress((void**)&up, g_up);

    __half *dns_h, *img_h, *wi_h, *wd_h;
    cudaGetSymbolAddress((void**)&dns_h, g_dns_h);
    cudaGetSymbolAddress((void**)&img_h, g_img_h);
    cudaGetSymbolAddress((void**)&wi_h, g_wi_h);
    cudaGetSymbolAddress((void**)&wd_h, g_wd_h);

    cudaFuncSetAttribute(gemm_h2, cudaFuncAttributeMaxDynamicSharedMemorySize, SMEM_DYN);

    tohalf4<<<NB_DNS + NB_IMG + 2 * NB_W, 256>>>(dns, dns_h, img, img_h,
                                                 W_i1, wi_h, W_d2, wd_h);

    gemm_h2<<<dim3(NCT, DNS_MT + IMG_MT), 256, SMEM_DYN>>>(
        dns_h, wd_h, w_att2 + HID, part2,
        img_h, wi_h, w_att1 + HID, part1);

    wsum_sm<<<dim3(BATCH, VSPLIT + USPLIT), 256>>>(part1, img, part2, dns, vp, up);
    reduce_uv<<<BATCH, 256>>>(vp, up, v, u);

    broadcast_kernel<<<(BATCH * SEQ * HID / 4) / 256, 256>>>(u, v, (float4*)out);
}

// round 12
// speedup vs baseline: 4.4177x; 1.0097x over previous
#include <cuda_runtime.h>
#include <cuda_fp16.h>
#include <math.h>
#include <stdint.h>

#define HID   1024
#define SEQ   512
#define RIMG  196
#define BATCH 32
#define NCT   8
#define MT    128
#define NT    128
#define KC    64
#define NCHUNK (HID / KC)
#define ROWB  144
#define VERB  (128 * ROWB)
#define STAGEB (2 * VERB)
#define WV_OFF  (2 * STAGEB)
#define RED_OFF (WV_OFF + 512)
#define SMEM_DYN (RED_OFF + 1024 + 256)

#define IMG_MT (BATCH * RIMG / MT)    // 49
#define DNS_MT (BATCH * SEQ / MT)     // 128

#define VSPLIT 7                      // img r-splits (196 = 7*28)
#define USPLIT 16                     // dns r-splits (512 = 16*32)

// ---------------- scratch ----------------
__device__ float g_part1[NCT * BATCH * RIMG];
__device__ float g_part2[NCT * BATCH * SEQ];
__device__ float g_vp[VSPLIT * BATCH * HID];
__device__ float g_up[USPLIT * BATCH * HID];

__device__ __half g_dns_h[BATCH * SEQ * HID];
__device__ __half g_img_h[BATCH * RIMG * HID];
__device__ __half g_wi_h[HID * HID];
__device__ __half g_wd_h[HID * HID];

// ---------------- helpers ----------------
__device__ __forceinline__ uint32_t smem_u32(const void* p) {
    uint32_t a;
    asm("{ .reg .u64 t; cvta.to.shared.u64 t, %1; cvt.u32.u64 %0, t; }" : "=r"(a) : "l"(p));
    return a;
}
__device__ __forceinline__ void ldsm4(uint32_t* r, uint32_t addr) {
    asm volatile("ldmatrix.sync.aligned.m8n8.x4.shared.b16 {%0,%1,%2,%3}, [%4];"
                 : "=r"(r[0]), "=r"(r[1]), "=r"(r[2]), "=r"(r[3]) : "r"(addr));
}
__device__ __forceinline__ void mma16816(float* c, const uint32_t* a,
                                         uint32_t b0, uint32_t b1) {
    asm volatile(
        "mma.sync.aligned.m16n8k16.row.col.f32.f16.f16.f32 "
        "{%0,%1,%2,%3}, {%4,%5,%6,%7}, {%8,%9}, {%0,%1,%2,%3};"
        : "+f"(c[0]), "+f"(c[1]), "+f"(c[2]), "+f"(c[3])
        : "r"(a[0]), "r"(a[1]), "r"(a[2]), "r"(a[3]), "r"(b0), "r"(b1));
}
#define CP16(s, g) \
    asm volatile("cp.async.cg.shared.global [%0], [%1], 16;" :: "r"(s), "l"(g) : "memory")
#define CP_COMMIT() asm volatile("cp.async.commit_group;" ::: "memory")

__device__ __forceinline__ float fast_tanh(float x) {
    return 1.f - 2.f / (__expf(2.f * x) + 1.f);
}
__device__ __forceinline__ float warpRedMax(float v) {
#pragma unroll
    for (int o = 16; o > 0; o >>= 1) v = fmaxf(v, __shfl_xor_sync(0xffffffffu, v, o));
    return v;
}
__device__ __forceinline__ float warpRedSum(float v) {
#pragma unroll
    for (int o = 16; o > 0; o >>= 1) v += __shfl_xor_sync(0xffffffffu, v, o);
    return v;
}

// ---------------------------------------------------------------------------
// fused fp32->fp16 convert, 16 floats/thread (MLP 4)
// ---------------------------------------------------------------------------
#define NB_DNS (BATCH * SEQ * HID / 4096)    // 4096
#define NB_IMG (BATCH * RIMG * HID / 4096)   // 1568
#define NB_W   (HID * HID / 4096)            // 256
__global__ __launch_bounds__(256)
void tohalf4(const float* __restrict__ i0, __half* __restrict__ o0,
             const float* __restrict__ i1, __half* __restrict__ o1,
             const float* __restrict__ i2, __half* __restrict__ o2,
             const float* __restrict__ i3, __half* __restrict__ o3)
{
    const int b = blockIdx.x;
    const float* in; __half* out; int base;
    if (b < NB_DNS)                       { in = i0; out = o0; base = b; }
    else if (b < NB_DNS + NB_IMG)         { in = i1; out = o1; base = b - NB_DNS; }
    else if (b < NB_DNS + NB_IMG + NB_W)  { in = i2; out = o2; base = b - NB_DNS - NB_IMG; }
    else                                  { in = i3; out = o3; base = b - NB_DNS - NB_IMG - NB_W; }
    const int i = base * 256 + threadIdx.x;
    const float4* p = (const float4*)in + (size_t)i * 4;
    float4 f[4];
#pragma unroll
    for (int j = 0; j < 4; j++) f[j] = __ldg(p + j);
    uint4* o = (uint4*)out + (size_t)i * 2;
#pragma unroll
    for (int g = 0; g < 2; g++) {
        float4 a = f[g * 2], c = f[g * 2 + 1];
        __half2 h0 = __floats2half2_rn(a.x, a.y);
        __half2 h1 = __floats2half2_rn(a.z, a.w);
        __half2 h2 = __floats2half2_rn(c.x, c.y);
        __half2 h3 = __floats2half2_rn(c.z, c.w);
        uint4 w;
        w.x = *reinterpret_cast<uint32_t*>(&h0);
        w.y = *reinterpret_cast<uint32_t*>(&h1);
        w.z = *reinterpret_cast<uint32_t*>(&h2);
        w.w = *reinterpret_cast<uint32_t*>(&h3);
        o[g] = w;
    }
}

// ---------------------------------------------------------------------------
// fused single-launch fp16 GEMM for BOTH score paths (unchanged).
// ---------------------------------------------------------------------------
__global__ __launch_bounds__(256, 2)
void gemm_h2(const __half* __restrict__ Xd, const __half* __restrict__ Wd,
             const float* __restrict__ wvd, float* __restrict__ partd,
             const __half* __restrict__ Xi, const __half* __restrict__ Wi,
             const float* __restrict__ wvi, float* __restrict__ parti)
{
    extern __shared__ char smem[];
    const uint32_t sb = smem_u32(smem);
    const int tid = threadIdx.x, lane = tid & 31, wid = tid >> 5;
    const int ntile = blockIdx.x;

    const __half *X, *W;
    const float* wvec;
    float* part;
    int mtile, Ntot;
    if (blockIdx.y < DNS_MT) {
        X = Xd; W = Wd; wvec = wvd; part = partd;
        mtile = blockIdx.y; Ntot = BATCH * SEQ;
    } else {
        X = Xi; W = Wi; wvec = wvi; part = parti;
        mtile = blockIdx.y - DNS_MT; Ntot = BATCH * RIMG;
    }

    float* wvsh = (float*)(smem + WV_OFF);
    float* red  = (float*)(smem + RED_OFF);
    if (tid < 128) wvsh[tid] = wvec[ntile * NT + tid];

    const int row  = tid >> 1;
    const int half = tid & 1;
    const char* pA = (const char*)(X + (size_t)(mtile * MT + row) * HID) + half * 64;
    const char* pB = (const char*)(W + (size_t)(ntile * NT + row) * HID) + half * 64;
    const uint32_t st = (uint32_t)(row * ROWB + half * 64);

    const int m_off = (wid & 3) * 32;
    const int n_off = (wid >> 2) * 64;
    const int lm_row  = lane & 15;
    const int lm_colb = (lane & 16) ? 16 : 0;

    float acc[2][8][4];
#pragma unroll
    for (int t = 0; t < 2; t++)
#pragma unroll
        for (int n = 0; n < 8; n++)
#pragma unroll
            for (int j = 0; j < 4; j++) acc[t][n][j] = 0.f;

#define ISSUE(ci)                                                  \
    do {                                                           \
        const uint32_t s0 = sb + ((ci) & 1) * STAGEB + st;         \
        const char* gA = pA + (size_t)(ci) * 128;                  \
        const char* gB = pB + (size_t)(ci) * 128;                  \
        CP16(s0,      gA);                                         \
        CP16(s0 + 16, gA + 16);                                    \
        CP16(s0 + 32, gA + 32);                                    \
        CP16(s0 + 48, gA + 48);                                    \
        CP16(s0 + VERB,      gB);                                  \
        CP16(s0 + VERB + 16, gB + 16);                             \
        CP16(s0 + VERB + 32, gB + 32);                             \
        CP16(s0 + VERB + 48, gB + 48);                             \
        CP_COMMIT();                                               \
    } while (0)

    ISSUE(0);

    for (int i = 0; i < NCHUNK; ++i) {
        asm volatile("cp.async.wait_group 0;" ::: "memory");
        __syncthreads();
        if (i + 1 < NCHUNK) ISSUE(i + 1);

        const uint32_t SA = sb + (i & 1) * STAGEB;
        const uint32_t SB = SA + VERB;
#pragma unroll
        for (int ks = 0; ks < 4; ks++) {
            const uint32_t aoff = (uint32_t)(ks * 32 + lm_colb);
            uint32_t af[2][4], bf[4][4];
#pragma unroll
            for (int t = 0; t < 2; t++)
                ldsm4(af[t], SA + (uint32_t)((m_off + t * 16 + lm_row) * ROWB) + aoff);
#pragma unroll
            for (int q = 0; q < 4; q++)
                ldsm4(bf[q], SB + (uint32_t)((n_off + q * 16 + lm_row) * ROWB) + aoff);
#pragma unroll
            for (int t = 0; t < 2; t++)
#pragma unroll
                for (int n8 = 0; n8 < 8; n8++) {
                    const int q = n8 >> 1, u = n8 & 1;
                    mma16816(acc[t][n8], af[t], bf[q][u], bf[q][u + 2]);
                }
        }
    }

    float s0[2] = {0.f, 0.f}, s1[2] = {0.f, 0.f};
#pragma unroll
    for (int t = 0; t < 2; t++)
#pragma unroll
        for (int n8 = 0; n8 < 8; n8++) {
            const float w0 = wvsh[n_off + n8 * 8 + (lane & 3) * 2];
            const float w1 = wvsh[n_off + n8 * 8 + (lane & 3) * 2 + 1];
            s0[t] = fmaf(fast_tanh(acc[t][n8][0]), w0, s0[t]);
            s0[t] = fmaf(fast_tanh(acc[t][n8][1]), w1, s0[t]);
            s1[t] = fmaf(fast_tanh(acc[t][n8][2]), w0, s1[t]);
            s1[t] = fmaf(fast_tanh(acc[t][n8][3]), w1, s1[t]);
        }
#pragma unroll
    for (int o = 1; o <= 2; o <<= 1) {
#pragma unroll
        for (int t = 0; t < 2; t++) {
            s0[t] += __shfl_xor_sync(0xffffffffu, s0[t], o);
            s1[t] += __shfl_xor_sync(0xffffffffu, s1[t], o);
        }
    }
    __syncthreads();
    if ((lane & 3) == 0) {
        const int r = lane >> 2;
        float* rw = red + (wid >> 2) * 128;
        rw[m_off + r]          = s0[0];
        rw[m_off + r + 8]      = s1[0];
        rw[m_off + 16 + r]     = s0[1];
        rw[m_off + 16 + r + 8] = s1[1];
    }
    __syncthreads();
    if (tid < 128)
        part[ntile * Ntot + mtile * MT + tid] = red[tid] + red[128 + tid];
}

// ---------------------------------------------------------------------------
// fused softmax + split-r weighted sum (unchanged from R11).
// ---------------------------------------------------------------------------
__global__ __launch_bounds__(256)
void wsum_sm(const float* __restrict__ part1, const float* __restrict__ img,
             const float* __restrict__ part2, const float* __restrict__ dns,
             float* __restrict__ vp, float* __restrict__ up)
{
    __shared__ float ws[SEQ];
    __shared__ float sh[8];
    const int b = blockIdx.x, y = blockIdx.y, t = threadIdx.x;

    const float* part; const float* X; float* outp;
    int r0, rn, n, N;
    if (y < VSPLIT) {
        part = part1; X = img; outp = vp + (size_t)y * BATCH * HID;
        r0 = y * (RIMG / VSPLIT); rn = RIMG / VSPLIT; n = RIMG; N = BATCH * RIMG;
    } else {
        const int s = y - VSPLIT;
        part = part2; X = dns; outp = up + (size_t)s * BATCH * HID;
        r0 = s * (SEQ / USPLIT); rn = SEQ / USPLIT; n = SEQ; N = BATCH * SEQ;
    }
    const int base = b * n;

    float m = -1e30f;
    for (int i = t; i < n; i += 256) {
        float x = 0.f;
#pragma unroll
        for (int c = 0; c < NCT; c++) x += part[c * N + base + i];
        ws[i] = x;
        m = fmaxf(m, x);
    }
    m = warpRedMax(m);
    if ((t & 31) == 0) sh[t >> 5] = m;
    __syncthreads();
    float M = sh[0];
#pragma unroll
    for (int q = 1; q < 8; q++) M = fmaxf(M, sh[q]);

    float sum = 0.f;
    for (int i = t; i < n; i += 256) {
        float e = expf(ws[i] - M);
        ws[i] = e;
        sum += e;
    }
    sum = warpRedSum(sum);
    __syncthreads();
    if ((t & 31) == 0) sh[t >> 5] = sum;
    __syncthreads();
    float S = 0.f;
#pragma unroll
    for (int q = 0; q < 8; q++) S += sh[q];
    const float inv = 1.f / S;
    __syncthreads();

    const float4* xb = (const float4*)(X + (size_t)b * n * HID) + (size_t)r0 * 256 + t;
    float4 acc = make_float4(0.f, 0.f, 0.f, 0.f);
#pragma unroll 4
    for (int r = 0; r < rn; r++) {
        const float wr = ws[r0 + r];
        const float4 x = __ldg(&xb[(size_t)r * 256]);
        acc.x = fmaf(wr, x.x, acc.x);
        acc.y = fmaf(wr, x.y, acc.y);
        acc.z = fmaf(wr, x.z, acc.z);
        acc.w = fmaf(wr, x.w, acc.w);
    }
    acc.x *= inv; acc.y *= inv; acc.z *= inv; acc.w *= inv;
    ((float4*)(outp + b * HID))[t] = acc;
}

// ---------------------------------------------------------------------------
// finalize: reduce partials -> u[b,:], v[b,:] in registers, then broadcast
// over the s-range of this block. grid (BATCH, 8); 256 threads = 1024 h.
// out[0 : B*S*H) = u (att_dns), out[B*S*H : ...) = v (att_img).
// ---------------------------------------------------------------------------
#define SCHUNK (SEQ / 8)    // 64
__global__ __launch_bounds__(256)
void finalize(const float* __restrict__ vp, const float* __restrict__ up,
              float4* __restrict__ out)
{
    const int b = blockIdx.x, sc = blockIdx.y, t = threadIdx.x;

    float4 sv = make_float4(0.f, 0.f, 0.f, 0.f);
#pragma unroll
    for (int s = 0; s < VSPLIT; s++) {
        float4 x = __ldg(((const float4*)(vp + (size_t)s * BATCH * HID + b * HID)) + t);
        sv.x += x.x; sv.y += x.y; sv.z += x.z; sv.w += x.w;
    }
    float4 su = make_float4(0.f, 0.f, 0.f, 0.f);
#pragma unroll
    for (int s = 0; s < USPLIT; s++) {
        float4 x = __ldg(((const float4*)(up + (size_t)s * BATCH * HID + b * HID)) + t);
        su.x += x.x; su.y += x.y; su.z += x.z; su.w += x.w;
    }

    float4* ou = out + ((size_t)b * SEQ + sc * SCHUNK) * 256 + t;
    float4* ov = ou + (size_t)BATCH * SEQ * 256;
#pragma unroll 4
    for (int s = 0; s < SCHUNK; s++) {
        ou[(size_t)s * 256] = su;
        ov[(size_t)s * 256] = sv;
    }
}

// ---------------------------------------------------------------------------
extern "C" void kernel_launch(void* const* d_in, const int* in_sizes, int n_in,
                              void* d_out, int out_size)
{
    const float* dns    = (const float*)d_in[0];
    const float* img    = (const float*)d_in[1];
    const float* W_i1   = (const float*)d_in[4];
    const float* w_att1 = (const float*)d_in[5];
    const float* W_d2   = (const float*)d_in[7];
    const float* w_att2 = (const float*)d_in[10];
    float* out = (float*)d_out;

    float *part1, *part2, *vp, *up;
    cudaGetSymbolAddress((void**)&part1, g_part1);
    cudaGetSymbolAddress((void**)&part2, g_part2);
    cudaGetSymbolAddress((void**)&vp, g_vp);
    cudaGetSymbolAddress((void**)&up, g_up);

    __half *dns_h, *img_h, *wi_h, *wd_h;
    cudaGetSymbolAddress((void**)&dns_h, g_dns_h);
    cudaGetSymbolAddress((void**)&img_h, g_img_h);
    cudaGetSymbolAddress((void**)&wi_h, g_wi_h);
    cudaGetSymbolAddress((void**)&wd_h, g_wd_h);

    cudaFuncSetAttribute(gemm_h2, cudaFuncAttributeMaxDynamicSharedMemorySize, SMEM_DYN);

    tohalf4<<<NB_DNS + NB_IMG + 2 * NB_W, 256>>>(dns, dns_h, img, img_h,
                                                 W_i1, wi_h, W_d2, wd_h);

    gemm_h2<<<dim3(NCT, DNS_MT + IMG_MT), 256, SMEM_DYN>>>(
        dns_h, wd_h, w_att2 + HID, part2,
        img_h, wi_h, w_att1 + HID, part1);

    wsum_sm<<<dim3(BATCH, VSPLIT + USPLIT), 256>>>(part1, img, part2, dns, vp, up);

    finalize<<<dim3(BATCH, 8), 256>>>(vp, up, (float4*)out);
}